// round 9
// baseline (speedup 1.0000x reference)
#include <cuda_runtime.h>
#include <cuda_bf16.h>
#include <cuda_fp16.h>
#include <cstdint>

#define Bc 4
#define Sc 4096
#define Dc 128
#define Kc 64
#define Vc 128
#define BSc (Bc*Sc)
#define OUTC 256

// ---------------- scratch ----------------
__device__ __nv_bfloat16 g_Qs[(size_t)BSc * 128];      // [hi64 | lo64] per token
__device__ __nv_bfloat16 g_Ks[(size_t)BSc * 128];
__device__ float         g_Vp[(size_t)BSc * Vc];
__device__ __half        g_Vt[(size_t)Bc * Vc * Sc];   // [b][v][s], V/denom, fp16
__device__ float         g_denom[BSc];

// ---------------- PTX helpers ----------------
__device__ __forceinline__ uint32_t smem_u32(const void* p) {
    uint32_t a;
    asm("{ .reg .u64 t; cvta.to.shared.u64 t, %1; cvt.u32.u64 %0, t; }" : "=r"(a) : "l"(p));
    return a;
}
#define CP16(dst, src) \
    asm volatile("cp.async.cg.shared.global [%0], [%1], 16;" :: "r"(dst), "l"(src))
#define CP_COMMIT() asm volatile("cp.async.commit_group;" ::: "memory")
#define CP_WAITG(n) asm volatile("cp.async.wait_group %0;" :: "n"(n) : "memory")
#define LDM_X4(d0, d1, d2, d3, a) \
    asm volatile("ldmatrix.sync.aligned.m8n8.x4.shared.b16 {%0,%1,%2,%3}, [%4];" \
        : "=r"(d0), "=r"(d1), "=r"(d2), "=r"(d3) : "r"(a))

__device__ __forceinline__ void mma_bf16(float* d, const uint32_t* a, const uint32_t* b) {
    asm volatile("mma.sync.aligned.m16n8k16.row.col.f32.bf16.bf16.f32 "
        "{%0,%1,%2,%3}, {%4,%5,%6,%7}, {%8,%9}, {%0,%1,%2,%3};"
        : "+f"(d[0]), "+f"(d[1]), "+f"(d[2]), "+f"(d[3])
        : "r"(a[0]), "r"(a[1]), "r"(a[2]), "r"(a[3]), "r"(b[0]), "r"(b[1]));
}
__device__ __forceinline__ void mma_f16(float* d, const uint32_t* a, const uint32_t* b) {
    asm volatile("mma.sync.aligned.m16n8k16.row.col.f32.f16.f16.f32 "
        "{%0,%1,%2,%3}, {%4,%5,%6,%7}, {%8,%9}, {%0,%1,%2,%3};"
        : "+f"(d[0]), "+f"(d[1]), "+f"(d[2]), "+f"(d[3])
        : "r"(a[0]), "r"(a[1]), "r"(a[2]), "r"(a[3]), "r"(b[0]), "r"(b[1]));
}
__device__ __forceinline__ uint32_t pack_h(__half a, __half b) {
    __half2 t; t.x = a; t.y = b;
    return *reinterpret_cast<uint32_t*>(&t);
}
__device__ __forceinline__ uint32_t pack_b(__nv_bfloat16 a, __nv_bfloat16 b) {
    __nv_bfloat162 t; t.x = a; t.y = b;
    return *reinterpret_cast<uint32_t*>(&t);
}

// exp(s/8) as 2^(s*C): ex2.approx.f16x2 + fp32 residual correction.
__device__ __forceinline__ uint32_t exp2h2(float t0, float t1) {
    __half2 th = __floats2half2_rn(t0, t1);
    uint32_t thu = *reinterpret_cast<uint32_t*>(&th);
    uint32_t eu;
    asm("ex2.approx.f16x2 %0, %1;" : "=r"(eu) : "r"(thu));
    float tl0 = t0 - __half2float(__low2half(th));
    float tl1 = t1 - __half2float(__high2half(th));
    __half2 c = __floats2half2_rn(fmaf(0.6931472f, tl0, 1.0f),
                                  fmaf(0.6931472f, tl1, 1.0f));
    __half2 e = *reinterpret_cast<__half2*>(&eu);
    e = __hmul2(e, c);
    return *reinterpret_cast<uint32_t*>(&e);
}

// causal (qt, group-of-8) decode, heaviest first; sum over qt of ceil((qt+1)/8) = 80
__device__ __forceinline__ void decode_qt(int bx, int& qt, int& g0, int& g1) {
    int lin = 79 - bx;
    int base = 0; qt = 0;
    for (;;) { int gq = (qt + 8) >> 3; if (lin < base + gq) break; base += gq; qt++; }
    g0 = (lin - base) * 8;
    g1 = min(qt + 1, g0 + 8);
}

// ---------------- kernel 1: projections (mma split-bf16) -------------------
#define PJ_A0 0
#define PJ_A1 34816
#define PJ_B0 69632
#define PJ_B1 104448
#define PJ_BIAS 139264
#define PJ_SMEM 139776

__global__ __launch_bounds__(256) void proj_kernel(
    const float* __restrict__ x,
    const float* __restrict__ Wq, const float* __restrict__ bq,
    const float* __restrict__ Wk, const float* __restrict__ bk,
    const float* __restrict__ Wv, const float* __restrict__ bv) {
    extern __shared__ char smem[];
    const uint32_t sb = smem_u32(smem);
    const int tid = threadIdx.x;
    const int wid = tid >> 5, lane = tid & 31;
    const int grp = lane >> 2, qr = lane & 3;
    const int wm = wid >> 1, wn = wid & 1;
    const int nh = blockIdx.y;
    const int t0 = blockIdx.x * 128;

    if (nh == 0) {
        int i = blockIdx.x * 256 + tid;
        if (i < BSc) g_denom[i] = 0.0f;
    }
    if (tid < 128) {
        float bvv = (nh == 0) ? ((tid < 64) ? bq[tid] : bk[tid - 64]) : bv[tid];
        ((float*)(smem + PJ_BIAS))[tid] = bvv;
    }

    #pragma unroll
    for (int i = 0; i < 16; i++) {
        int idx = tid + i * 256;
        int r = idx >> 5, c4 = idx & 31;
        int ch = c4 >> 4, cc = c4 & 15;
        float4 a = *(const float4*)&x[(size_t)(t0 + r) * 128 + c4 * 4];
        __nv_bfloat16 h0 = __float2bfloat16(a.x), h1 = __float2bfloat16(a.y);
        __nv_bfloat16 h2 = __float2bfloat16(a.z), h3 = __float2bfloat16(a.w);
        uint2 hi = make_uint2(pack_b(h0, h1), pack_b(h2, h3));
        uint2 lo = make_uint2(
            pack_b(__float2bfloat16(a.x - __bfloat162float(h0)),
                   __float2bfloat16(a.y - __bfloat162float(h1))),
            pack_b(__float2bfloat16(a.z - __bfloat162float(h2)),
                   __float2bfloat16(a.w - __bfloat162float(h3))));
        char* ab = smem + (ch ? PJ_A1 : PJ_A0) + r * 272 + cc * 8;
        *(uint2*)ab = hi;
        *(uint2*)(ab + 128) = lo;

        const float* wsrc = (nh == 0)
            ? ((r < 64) ? (Wq + (size_t)r * 128) : (Wk + (size_t)(r - 64) * 128))
            : (Wv + (size_t)r * 128);
        float4 w = *(const float4*)&wsrc[c4 * 4];
        __nv_bfloat16 g0 = __float2bfloat16(w.x), g1 = __float2bfloat16(w.y);
        __nv_bfloat16 g2 = __float2bfloat16(w.z), g3 = __float2bfloat16(w.w);
        uint2 whi = make_uint2(pack_b(g0, g1), pack_b(g2, g3));
        uint2 wlo = make_uint2(
            pack_b(__float2bfloat16(w.x - __bfloat162float(g0)),
                   __float2bfloat16(w.y - __bfloat162float(g1))),
            pack_b(__float2bfloat16(w.z - __bfloat162float(g2)),
                   __float2bfloat16(w.w - __bfloat162float(g3))));
        char* bb = smem + (ch ? PJ_B1 : PJ_B0) + r * 272 + cc * 8;
        *(uint2*)bb = whi;
        *(uint2*)(bb + 128) = wlo;
    }
    __syncthreads();

    float acc[2][8][4] = {};
    const uint32_t aBase = sb + PJ_A0 + (wm*32 + (lane & 15))*272 + (lane >> 4)*16;
    const uint32_t bBase = sb + PJ_B0 + (wn*64 + (lane & 15))*272 + (lane >> 4)*16;
    const int aT[3] = {0, 1, 0}, bT[3] = {0, 0, 1};

    #pragma unroll
    for (int ch = 0; ch < 2; ch++) {
        #pragma unroll
        for (int t = 0; t < 3; t++) {
            #pragma unroll
            for (int ks = 0; ks < 4; ks++) {
                const uint32_t aOff = (uint32_t)(ch*34816 + aT[t]*128 + ks*32);
                const uint32_t bOff = (uint32_t)(ch*34816 + bT[t]*128 + ks*32);
                uint32_t afr[2][4];
                #pragma unroll
                for (int ma = 0; ma < 2; ma++)
                    LDM_X4(afr[ma][0], afr[ma][1], afr[ma][2], afr[ma][3],
                           aBase + ma*16*272 + aOff);
                uint32_t bfr[8][2];
                #pragma unroll
                for (int ng = 0; ng < 4; ng++) {
                    uint32_t d0, d1, d2, d3;
                    LDM_X4(d0, d1, d2, d3, bBase + ng*16*272 + bOff);
                    bfr[2*ng][0]   = d0; bfr[2*ng][1]   = d2;
                    bfr[2*ng+1][0] = d1; bfr[2*ng+1][1] = d3;
                }
                #pragma unroll
                for (int ma = 0; ma < 2; ma++)
                    #pragma unroll
                    for (int na = 0; na < 8; na++)
                        mma_bf16(acc[ma][na], afr[ma], bfr[na]);
            }
        }
    }
    __syncthreads();

    float* stage = (float*)smem;                 // [128][136]
    const float* biasS = (const float*)(smem + PJ_BIAS);
    #pragma unroll
    for (int ma = 0; ma < 2; ma++) {
        const int r0 = wm*32 + ma*16 + grp;
        #pragma unroll
        for (int na = 0; na < 8; na++) {
            const int c0 = wn*64 + na*8 + qr*2;
            stage[r0*136 + c0]     = acc[ma][na][0] + biasS[c0];
            stage[r0*136 + c0 + 1] = acc[ma][na][1] + biasS[c0 + 1];
            stage[(r0+8)*136 + c0]     = acc[ma][na][2] + biasS[c0];
            stage[(r0+8)*136 + c0 + 1] = acc[ma][na][3] + biasS[c0 + 1];
        }
    }
    __syncthreads();

    const int r = tid >> 1, h = tid & 1;
    if (nh == 0) {
        uint32_t hp[32], lp[32];
        #pragma unroll
        for (int k = 0; k < 32; k++) {
            float v0 = stage[r*136 + h*64 + 2*k];
            float v1 = stage[r*136 + h*64 + 2*k + 1];
            __nv_bfloat16 b0 = __float2bfloat16(v0), b1 = __float2bfloat16(v1);
            hp[k] = pack_b(b0, b1);
            lp[k] = pack_b(__float2bfloat16(v0 - __bfloat162float(b0)),
                           __float2bfloat16(v1 - __bfloat162float(b1)));
        }
        __nv_bfloat16* dstrow = (h == 0 ? g_Qs : g_Ks) + (size_t)(t0 + r) * 128;
        uint4* dh = (uint4*)dstrow;
        uint4* dl = (uint4*)(dstrow + 64);
        #pragma unroll
        for (int k = 0; k < 8; k++) { dh[k] = ((uint4*)hp)[k]; dl[k] = ((uint4*)lp)[k]; }
    } else {
        #pragma unroll
        for (int k = 0; k < 16; k++) {
            float4 v = *(const float4*)&stage[r*136 + h*64 + 4*k];
            *(float4*)&g_Vp[(size_t)(t0 + r) * 128 + h*64 + 4*k] = v;
        }
    }
}

// ---------------- kernel 2: denom (pipelined, no E store) ------------------
// grid (80, 4). Q resident; K double-buffered. Column sums via shfl + atomics.
#define DNQ 0
#define DNK0 34816
#define DNK1 69632
#define DN_SMEM 104448

__global__ __launch_bounds__(256) void denom_kernel() {
    extern __shared__ char smem[];
    const uint32_t sb = smem_u32(smem);
    const int tid = threadIdx.x;
    const int wid = tid >> 5, lane = tid & 31;
    const int grp = lane >> 2, qr = lane & 3;
    const int wm = wid >> 1, wn = wid & 1;
    const int b = blockIdx.y;

    int qt, g0, g1;
    decode_qt(blockIdx.x, qt, g0, g1);
    const int nk = g1 - g0;
    const int q0 = qt * 128;

    const char* Qsrc = (const char*)(g_Qs + (size_t)(b * Sc + q0) * 128);
    const char* Kbase = (const char*)(g_Ks + (size_t)b * Sc * 128);

    for (int idx = tid; idx < 2048; idx += 256) {
        int r = idx >> 4, ch = idx & 15;
        CP16(sb + DNQ + r*272 + ch*16, Qsrc + r*256 + ch*16);
        CP16(sb + DNK0 + r*272 + ch*16, Kbase + (size_t)(g0*128 + r)*256 + ch*16);
    }
    CP_COMMIT();

    const uint32_t aBase = sb + DNQ + (wm*32 + (lane & 15))*272 + (lane >> 4)*16;
    const uint32_t lmRow = (uint32_t)((wn*64 + (lane & 15))*272 + (lane >> 4)*16);
    const int aT[3] = {0, 1, 0}, bT[3] = {0, 0, 1};
    const float C = 0.18033688011112042f;   // 0.125 * log2(e)

    for (int i = 0; i < nk; i++) {
        const uint32_t kbuf = (i & 1) ? DNK1 : DNK0;
        if (i + 1 < nk) {
            const uint32_t nbuf = ((i + 1) & 1) ? DNK1 : DNK0;
            const size_t joff = (size_t)((g0 + i + 1) * 128) * 256;
            for (int idx = tid; idx < 2048; idx += 256) {
                int r = idx >> 4, ch = idx & 15;
                CP16(sb + nbuf + r*272 + ch*16, Kbase + joff + r*256 + ch*16);
            }
            CP_COMMIT();
            CP_WAITG(1);
        } else {
            CP_WAITG(0);
        }
        __syncthreads();

        float acc[2][8][4] = {};
        const uint32_t bBase = sb + kbuf + lmRow;
        #pragma unroll
        for (int t = 0; t < 3; t++) {
            #pragma unroll
            for (int ks = 0; ks < 4; ks++) {
                const uint32_t aOff = (uint32_t)(aT[t]*128 + ks*32);
                const uint32_t bOff = (uint32_t)(bT[t]*128 + ks*32);
                uint32_t afr[2][4];
                #pragma unroll
                for (int ma = 0; ma < 2; ma++)
                    LDM_X4(afr[ma][0], afr[ma][1], afr[ma][2], afr[ma][3],
                           aBase + ma*16*272 + aOff);
                uint32_t bfr[8][2];
                #pragma unroll
                for (int ng = 0; ng < 4; ng++) {
                    uint32_t d0, d1, d2, d3;
                    LDM_X4(d0, d1, d2, d3, bBase + ng*16*272 + bOff);
                    bfr[2*ng][0]   = d0; bfr[2*ng][1]   = d2;
                    bfr[2*ng+1][0] = d1; bfr[2*ng+1][1] = d3;
                }
                #pragma unroll
                for (int ma = 0; ma < 2; ma++)
                    #pragma unroll
                    for (int na = 0; na < 8; na++)
                        mma_bf16(acc[ma][na], afr[ma], bfr[na]);
            }
        }

        // exp + in-register column sums
        const int j0 = (g0 + i) * 128;
        float cs0[8] = {}, cs1[8] = {};
        #pragma unroll
        for (int ma = 0; ma < 2; ma++) {
            const int qlo = q0 + wm*32 + ma*16 + grp, qhi = qlo + 8;
            #pragma unroll
            for (int na = 0; na < 8; na++) {
                const int jc = j0 + wn*64 + na*8 + qr*2;
                float t0 = (jc     <= qlo) ? acc[ma][na][0] * C : -1000.0f;
                float t1 = (jc + 1 <= qlo) ? acc[ma][na][1] * C : -1000.0f;
                float t2 = (jc     <= qhi) ? acc[ma][na][2] * C : -1000.0f;
                float t3 = (jc + 1 <= qhi) ? acc[ma][na][3] * C : -1000.0f;
                uint32_t u0 = exp2h2(t0, t1), u1 = exp2h2(t2, t3);
                __half2 e0 = *reinterpret_cast<__half2*>(&u0);
                __half2 e1 = *reinterpret_cast<__half2*>(&u1);
                cs0[na] += __low2float(e0)  + __low2float(e1);
                cs1[na] += __high2float(e0) + __high2float(e1);
            }
        }
        // reduce over grp lanes (rows) then atomic add
        #pragma unroll
        for (int na = 0; na < 8; na++) {
            #pragma unroll
            for (int m = 4; m <= 16; m <<= 1) {
                cs0[na] += __shfl_xor_sync(0xFFFFFFFFu, cs0[na], m);
                cs1[na] += __shfl_xor_sync(0xFFFFFFFFu, cs1[na], m);
            }
        }
        if (grp == 0) {
            #pragma unroll
            for (int na = 0; na < 8; na++) {
                const int jc = j0 + wn*64 + na*8 + qr*2;
                atomicAdd(&g_denom[b * Sc + jc],     cs0[na]);
                atomicAdd(&g_denom[b * Sc + jc + 1], cs1[na]);
            }
        }
        __syncthreads();
    }
}

// ---------------- kernel 3: vprep ----------------
__global__ __launch_bounds__(256) void vprep_kernel() {
    __shared__ float tile[32][133];
    __shared__ float invs[32];
    const int b = blockIdx.y, s0 = blockIdx.x * 32, tid = threadIdx.x;
    if (tid < 32) invs[tid] = 1.0f / g_denom[b * Sc + s0 + tid];
    __syncthreads();
    #pragma unroll
    for (int i = 0; i < 16; i++) {
        int idx = tid + i * 256;
        int r = idx >> 7, c = idx & 127;
        tile[r][c] = g_Vp[(size_t)(b * Sc + s0 + r) * Vc + c] * invs[r];
    }
    __syncthreads();
    const int v = tid >> 1, h = tid & 1;
    uint32_t packs[8];
    #pragma unroll
    for (int k = 0; k < 8; k++)
        packs[k] = pack_h(__float2half(tile[h*16 + 2*k][v]),
                          __float2half(tile[h*16 + 2*k + 1][v]));
    uint4* dst = (uint4*)(g_Vt + (size_t)(b * Vc + v) * Sc + s0 + h*16);
    dst[0] = ((uint4*)packs)[0];
    dst[1] = ((uint4*)packs)[1];
}

// ---------------- kernel 4: concat ----------------
__global__ __launch_bounds__(256) void concat_kernel(const float* __restrict__ x,
                                                     float* __restrict__ out) {
    const int base = blockIdx.x * 256 + threadIdx.x;
    #pragma unroll
    for (int i = 0; i < 16; i++) {
        int idx = base + i * 65536;
        int c4 = idx & 63;
        int t = idx >> 6;
        float4 v = make_float4(0.f, 0.f, 0.f, 0.f);
        if (c4 < 32) v = ((const float4*)x)[(size_t)t * 32 + c4];
        ((float4*)out)[idx] = v;
    }
}

// ---------------- kernel 5: fused scores+attn (recompute, no E) ------------
// grid (80, 4). 8 warps x 16 q-rows. Q resident; K,Vt double-buffered.
#define FQ 0
#define FK0 34816
#define FK1 69632
#define FV0 104448
#define FV1 139264
#define F_SMEM 174080

__global__ __launch_bounds__(256) void fused_kernel(float* __restrict__ out) {
    extern __shared__ char smem[];
    const uint32_t sb = smem_u32(smem);
    const int tid = threadIdx.x;
    const int wid = tid >> 5, lane = tid & 31;
    const int grp = lane >> 2, qr = lane & 3;
    const int b = blockIdx.y;

    int qt, g0, g1;
    decode_qt(blockIdx.x, qt, g0, g1);
    const int nk = g1 - g0;
    const int q0 = qt * 128;

    const char* Qsrc = (const char*)(g_Qs + (size_t)(b * Sc + q0) * 128);
    const char* Kbase = (const char*)(g_Ks + (size_t)b * Sc * 128);
    const char* Vbase = (const char*)g_Vt + (size_t)b * Vc * Sc * 2;

    // initial fill: Q + K[0] + V[0]
    for (int idx = tid; idx < 2048; idx += 256) {
        int r = idx >> 4, ch = idx & 15;
        CP16(sb + FQ + r*272 + ch*16, Qsrc + r*256 + ch*16);
        CP16(sb + FK0 + r*272 + ch*16, Kbase + (size_t)(g0*128 + r)*256 + ch*16);
        CP16(sb + FV0 + r*272 + ch*16, Vbase + (size_t)r*Sc*2 + g0*256 + ch*16);
    }
    CP_COMMIT();

    const uint32_t aBase = sb + FQ + (wid*16 + (lane & 15))*272 + (lane >> 4)*16;
    const uint32_t lmRow = (uint32_t)(((lane & 15))*272 + (lane >> 4)*16);
    const int aT[3] = {0, 1, 0}, bT[3] = {0, 0, 1};
    const float C = 0.18033688011112042f;

    float oacc[16][4] = {};

    for (int i = 0; i < nk; i++) {
        const uint32_t kbuf = (i & 1) ? FK1 : FK0;
        const uint32_t vbuf = (i & 1) ? FV1 : FV0;
        if (i + 1 < nk) {
            const uint32_t nkb = ((i + 1) & 1) ? FK1 : FK0;
            const uint32_t nvb = ((i + 1) & 1) ? FV1 : FV0;
            const size_t joff = (size_t)((g0 + i + 1) * 128) * 256;
            const int jcol = (g0 + i + 1) * 256;
            for (int idx = tid; idx < 2048; idx += 256) {
                int r = idx >> 4, ch = idx & 15;
                CP16(sb + nkb + r*272 + ch*16, Kbase + joff + r*256 + ch*16);
                CP16(sb + nvb + r*272 + ch*16, Vbase + (size_t)r*Sc*2 + jcol + ch*16);
            }
            CP_COMMIT();
            CP_WAITG(1);
        } else {
            CP_WAITG(0);
        }
        __syncthreads();

        // MMA1: scores 16 x 128 per warp, split bf16 (3 terms x 4 ksteps)
        float acc[16][4] = {};
        const uint32_t bK = sb + kbuf + lmRow;
        #pragma unroll
        for (int t = 0; t < 3; t++) {
            #pragma unroll
            for (int ks = 0; ks < 4; ks++) {
                const uint32_t aOff = (uint32_t)(aT[t]*128 + ks*32);
                const uint32_t bOff = (uint32_t)(bT[t]*128 + ks*32);
                uint32_t afr[4];
                LDM_X4(afr[0], afr[1], afr[2], afr[3], aBase + aOff);
                #pragma unroll
                for (int ng = 0; ng < 8; ng++) {
                    uint32_t d0, d1, d2, d3;
                    LDM_X4(d0, d1, d2, d3, bK + ng*16*272 + bOff);
                    uint32_t b0[2] = {d0, d2}, b1[2] = {d1, d3};
                    mma_bf16(acc[2*ng],     afr, b0);
                    mma_bf16(acc[2*ng + 1], afr, b1);
                }
            }
        }

        // exp -> P fragments (fp16x2 packed == A-frag layout for MMA2)
        const int j0 = (g0 + i) * 128;
        const int qlo = q0 + wid*16 + grp, qhi = qlo + 8;
        uint32_t P[16][2];
        #pragma unroll
        for (int na = 0; na < 16; na++) {
            const int jc = j0 + na*8 + qr*2;
            float t0 = (jc     <= qlo) ? acc[na][0] * C : -1000.0f;
            float t1 = (jc + 1 <= qlo) ? acc[na][1] * C : -1000.0f;
            float t2 = (jc     <= qhi) ? acc[na][2] * C : -1000.0f;
            float t3 = (jc + 1 <= qhi) ? acc[na][3] * C : -1000.0f;
            P[na][0] = exp2h2(t0, t1);
            P[na][1] = exp2h2(t2, t3);
        }

        // MMA2: out += P @ Vt^T (contraction over j)
        const uint32_t bV = sb + vbuf + lmRow;
        #pragma unroll
        for (int ks = 0; ks < 8; ks++) {
            uint32_t afr[4] = {P[2*ks][0], P[2*ks][1], P[2*ks+1][0], P[2*ks+1][1]};
            const uint32_t kOff = (uint32_t)(ks * 32);
            #pragma unroll
            for (int ng = 0; ng < 8; ng++) {
                uint32_t d0, d1, d2, d3;
                LDM_X4(d0, d1, d2, d3, bV + ng*16*272 + kOff);
                uint32_t b0[2] = {d0, d2}, b1[2] = {d1, d3};
                mma_f16(oacc[2*ng],     afr, b0);
                mma_f16(oacc[2*ng + 1], afr, b1);
            }
        }
        __syncthreads();
    }

    // epilogue: atomic adds into out[:, 128:256]
    const int r0 = q0 + wid*16 + grp;
    #pragma unroll
    for (int na = 0; na < 16; na++) {
        const int v0 = na*8 + qr*2;
        atomicAdd(&out[(size_t)(b*Sc + r0)*OUTC + Dc + v0],     oacc[na][0]);
        atomicAdd(&out[(size_t)(b*Sc + r0)*OUTC + Dc + v0 + 1], oacc[na][1]);
        atomicAdd(&out[(size_t)(b*Sc + r0 + 8)*OUTC + Dc + v0],     oacc[na][2]);
        atomicAdd(&out[(size_t)(b*Sc + r0 + 8)*OUTC + Dc + v0 + 1], oacc[na][3]);
    }
}

// ---------------- launch ----------------
extern "C" void kernel_launch(void* const* d_in, const int* in_sizes, int n_in,
                              void* d_out, int out_size) {
    const float* x  = (const float*)d_in[0];
    const float* Wq = (const float*)d_in[1];
    const float* bq = (const float*)d_in[2];
    const float* Wk = (const float*)d_in[3];
    const float* bk = (const float*)d_in[4];
    const float* Wv = (const float*)d_in[5];
    const float* bv = (const float*)d_in[6];
    float* out = (float*)d_out;

    cudaFuncSetAttribute(proj_kernel,  cudaFuncAttributeMaxDynamicSharedMemorySize, PJ_SMEM);
    cudaFuncSetAttribute(denom_kernel, cudaFuncAttributeMaxDynamicSharedMemorySize, DN_SMEM);
    cudaFuncSetAttribute(fused_kernel, cudaFuncAttributeMaxDynamicSharedMemorySize, F_SMEM);

    proj_kernel<<<dim3(BSc / 128, 2), 256, PJ_SMEM>>>(x, Wq, bq, Wk, bk, Wv, bv);
    denom_kernel<<<dim3(80, Bc), 256, DN_SMEM>>>();
    vprep_kernel<<<dim3(Sc / 32, Bc), 256>>>();
    concat_kernel<<<256, 256>>>(x, out);
    fused_kernel<<<dim3(80, Bc), 256, F_SMEM>>>(out);
}

// round 10
// speedup vs baseline: 1.0211x; 1.0211x over previous
#include <cuda_runtime.h>
#include <cuda_bf16.h>
#include <cuda_fp16.h>
#include <cstdint>

#define Bc 4
#define Sc 4096
#define Dc 128
#define Kc 64
#define Vc 128
#define BSc (Bc*Sc)
#define OUTC 256

// ---------------- scratch ----------------
__device__ __nv_bfloat16 g_Qs[(size_t)BSc * 128];      // [hi64 | lo64] per token
__device__ __nv_bfloat16 g_Ks[(size_t)BSc * 128];
__device__ float         g_Vp[(size_t)BSc * Vc];
__device__ __half        g_E[(size_t)Bc * Sc * Sc];    // exp(scores), causal zeros
__device__ __half        g_Vt[(size_t)Bc * Vc * Sc];   // [b][v][s], V/denom, fp16
__device__ float         g_denom[BSc];

// ---------------- PTX helpers ----------------
__device__ __forceinline__ uint32_t smem_u32(const void* p) {
    uint32_t a;
    asm("{ .reg .u64 t; cvta.to.shared.u64 t, %1; cvt.u32.u64 %0, t; }" : "=r"(a) : "l"(p));
    return a;
}
#define CP16(dst, src) \
    asm volatile("cp.async.cg.shared.global [%0], [%1], 16;" :: "r"(dst), "l"(src))
#define CP_COMMIT() asm volatile("cp.async.commit_group;" ::: "memory")
#define CP_WAITG(n) asm volatile("cp.async.wait_group %0;" :: "n"(n) : "memory")
#define LDM_X4(d0, d1, d2, d3, a) \
    asm volatile("ldmatrix.sync.aligned.m8n8.x4.shared.b16 {%0,%1,%2,%3}, [%4];" \
        : "=r"(d0), "=r"(d1), "=r"(d2), "=r"(d3) : "r"(a))

__device__ __forceinline__ void mma_bf16(float* d, const uint32_t* a, const uint32_t* b) {
    asm volatile("mma.sync.aligned.m16n8k16.row.col.f32.bf16.bf16.f32 "
        "{%0,%1,%2,%3}, {%4,%5,%6,%7}, {%8,%9}, {%0,%1,%2,%3};"
        : "+f"(d[0]), "+f"(d[1]), "+f"(d[2]), "+f"(d[3])
        : "r"(a[0]), "r"(a[1]), "r"(a[2]), "r"(a[3]), "r"(b[0]), "r"(b[1]));
}
__device__ __forceinline__ void mma_f16(float* d, const uint32_t* a, const uint32_t* b) {
    asm volatile("mma.sync.aligned.m16n8k16.row.col.f32.f16.f16.f32 "
        "{%0,%1,%2,%3}, {%4,%5,%6,%7}, {%8,%9}, {%0,%1,%2,%3};"
        : "+f"(d[0]), "+f"(d[1]), "+f"(d[2]), "+f"(d[3])
        : "r"(a[0]), "r"(a[1]), "r"(a[2]), "r"(a[3]), "r"(b[0]), "r"(b[1]));
}
__device__ __forceinline__ uint32_t pack_h(__half a, __half b) {
    __half2 t; t.x = a; t.y = b;
    return *reinterpret_cast<uint32_t*>(&t);
}
__device__ __forceinline__ uint32_t pack_b(__nv_bfloat16 a, __nv_bfloat16 b) {
    __nv_bfloat162 t; t.x = a; t.y = b;
    return *reinterpret_cast<uint32_t*>(&t);
}

// exp(s/8) as 2^(s*C): ex2.approx.f16x2 + fp32 residual correction.
__device__ __forceinline__ uint32_t exp2h2(float t0, float t1) {
    __half2 th = __floats2half2_rn(t0, t1);
    uint32_t thu = *reinterpret_cast<uint32_t*>(&th);
    uint32_t eu;
    asm("ex2.approx.f16x2 %0, %1;" : "=r"(eu) : "r"(thu));
    float tl0 = t0 - __half2float(__low2half(th));
    float tl1 = t1 - __half2float(__high2half(th));
    __half2 c = __floats2half2_rn(fmaf(0.6931472f, tl0, 1.0f),
                                  fmaf(0.6931472f, tl1, 1.0f));
    __half2 e = *reinterpret_cast<__half2*>(&eu);
    e = __hmul2(e, c);
    return *reinterpret_cast<uint32_t*>(&e);
}

// causal (qt, group-of-8) decode, heaviest first; sum over qt of ceil((qt+1)/8) = 80
__device__ __forceinline__ void decode_qt(int bx, int& qt, int& g0, int& g1) {
    int lin = 79 - bx;
    int base = 0; qt = 0;
    for (;;) { int gq = (qt + 8) >> 3; if (lin < base + gq) break; base += gq; qt++; }
    g0 = (lin - base) * 8;
    g1 = min(qt + 1, g0 + 8);
}

// ---------------- kernel 1: projections (mma split-bf16) -------------------
#define PJ_A0 0
#define PJ_A1 34816
#define PJ_B0 69632
#define PJ_B1 104448
#define PJ_BIAS 139264
#define PJ_SMEM 139776

__global__ __launch_bounds__(256) void proj_kernel(
    const float* __restrict__ x,
    const float* __restrict__ Wq, const float* __restrict__ bq,
    const float* __restrict__ Wk, const float* __restrict__ bk,
    const float* __restrict__ Wv, const float* __restrict__ bv) {
    extern __shared__ char smem[];
    const uint32_t sb = smem_u32(smem);
    const int tid = threadIdx.x;
    const int wid = tid >> 5, lane = tid & 31;
    const int grp = lane >> 2, qr = lane & 3;
    const int wm = wid >> 1, wn = wid & 1;
    const int nh = blockIdx.y;
    const int t0 = blockIdx.x * 128;

    if (nh == 0) {
        int i = blockIdx.x * 256 + tid;
        if (i < BSc) g_denom[i] = 0.0f;
    }
    if (tid < 128) {
        float bvv = (nh == 0) ? ((tid < 64) ? bq[tid] : bk[tid - 64]) : bv[tid];
        ((float*)(smem + PJ_BIAS))[tid] = bvv;
    }

    #pragma unroll
    for (int i = 0; i < 16; i++) {
        int idx = tid + i * 256;
        int r = idx >> 5, c4 = idx & 31;
        int ch = c4 >> 4, cc = c4 & 15;
        float4 a = *(const float4*)&x[(size_t)(t0 + r) * 128 + c4 * 4];
        __nv_bfloat16 h0 = __float2bfloat16(a.x), h1 = __float2bfloat16(a.y);
        __nv_bfloat16 h2 = __float2bfloat16(a.z), h3 = __float2bfloat16(a.w);
        uint2 hi = make_uint2(pack_b(h0, h1), pack_b(h2, h3));
        uint2 lo = make_uint2(
            pack_b(__float2bfloat16(a.x - __bfloat162float(h0)),
                   __float2bfloat16(a.y - __bfloat162float(h1))),
            pack_b(__float2bfloat16(a.z - __bfloat162float(h2)),
                   __float2bfloat16(a.w - __bfloat162float(h3))));
        char* ab = smem + (ch ? PJ_A1 : PJ_A0) + r * 272 + cc * 8;
        *(uint2*)ab = hi;
        *(uint2*)(ab + 128) = lo;

        const float* wsrc = (nh == 0)
            ? ((r < 64) ? (Wq + (size_t)r * 128) : (Wk + (size_t)(r - 64) * 128))
            : (Wv + (size_t)r * 128);
        float4 w = *(const float4*)&wsrc[c4 * 4];
        __nv_bfloat16 g0 = __float2bfloat16(w.x), g1 = __float2bfloat16(w.y);
        __nv_bfloat16 g2 = __float2bfloat16(w.z), g3 = __float2bfloat16(w.w);
        uint2 whi = make_uint2(pack_b(g0, g1), pack_b(g2, g3));
        uint2 wlo = make_uint2(
            pack_b(__float2bfloat16(w.x - __bfloat162float(g0)),
                   __float2bfloat16(w.y - __bfloat162float(g1))),
            pack_b(__float2bfloat16(w.z - __bfloat162float(g2)),
                   __float2bfloat16(w.w - __bfloat162float(g3))));
        char* bb = smem + (ch ? PJ_B1 : PJ_B0) + r * 272 + cc * 8;
        *(uint2*)bb = whi;
        *(uint2*)(bb + 128) = wlo;
    }
    __syncthreads();

    float acc[2][8][4] = {};
    const uint32_t aBase = sb + PJ_A0 + (wm*32 + (lane & 15))*272 + (lane >> 4)*16;
    const uint32_t bBase = sb + PJ_B0 + (wn*64 + (lane & 15))*272 + (lane >> 4)*16;
    const int aT[3] = {0, 1, 0}, bT[3] = {0, 0, 1};

    #pragma unroll
    for (int ch = 0; ch < 2; ch++) {
        #pragma unroll
        for (int t = 0; t < 3; t++) {
            #pragma unroll
            for (int ks = 0; ks < 4; ks++) {
                const uint32_t aOff = (uint32_t)(ch*34816 + aT[t]*128 + ks*32);
                const uint32_t bOff = (uint32_t)(ch*34816 + bT[t]*128 + ks*32);
                uint32_t afr[2][4];
                #pragma unroll
                for (int ma = 0; ma < 2; ma++)
                    LDM_X4(afr[ma][0], afr[ma][1], afr[ma][2], afr[ma][3],
                           aBase + ma*16*272 + aOff);
                uint32_t bfr[8][2];
                #pragma unroll
                for (int ng = 0; ng < 4; ng++) {
                    uint32_t d0, d1, d2, d3;
                    LDM_X4(d0, d1, d2, d3, bBase + ng*16*272 + bOff);
                    bfr[2*ng][0]   = d0; bfr[2*ng][1]   = d2;
                    bfr[2*ng+1][0] = d1; bfr[2*ng+1][1] = d3;
                }
                #pragma unroll
                for (int ma = 0; ma < 2; ma++)
                    #pragma unroll
                    for (int na = 0; na < 8; na++)
                        mma_bf16(acc[ma][na], afr[ma], bfr[na]);
            }
        }
    }
    __syncthreads();

    float* stage = (float*)smem;                 // [128][136]
    const float* biasS = (const float*)(smem + PJ_BIAS);
    #pragma unroll
    for (int ma = 0; ma < 2; ma++) {
        const int r0 = wm*32 + ma*16 + grp;
        #pragma unroll
        for (int na = 0; na < 8; na++) {
            const int c0 = wn*64 + na*8 + qr*2;
            stage[r0*136 + c0]     = acc[ma][na][0] + biasS[c0];
            stage[r0*136 + c0 + 1] = acc[ma][na][1] + biasS[c0 + 1];
            stage[(r0+8)*136 + c0]     = acc[ma][na][2] + biasS[c0];
            stage[(r0+8)*136 + c0 + 1] = acc[ma][na][3] + biasS[c0 + 1];
        }
    }
    __syncthreads();

    const int r = tid >> 1, h = tid & 1;
    if (nh == 0) {
        uint32_t hp[32], lp[32];
        #pragma unroll
        for (int k = 0; k < 32; k++) {
            float v0 = stage[r*136 + h*64 + 2*k];
            float v1 = stage[r*136 + h*64 + 2*k + 1];
            __nv_bfloat16 b0 = __float2bfloat16(v0), b1 = __float2bfloat16(v1);
            hp[k] = pack_b(b0, b1);
            lp[k] = pack_b(__float2bfloat16(v0 - __bfloat162float(b0)),
                           __float2bfloat16(v1 - __bfloat162float(b1)));
        }
        __nv_bfloat16* dstrow = (h == 0 ? g_Qs : g_Ks) + (size_t)(t0 + r) * 128;
        uint4* dh = (uint4*)dstrow;
        uint4* dl = (uint4*)(dstrow + 64);
        #pragma unroll
        for (int k = 0; k < 8; k++) { dh[k] = ((uint4*)hp)[k]; dl[k] = ((uint4*)lp)[k]; }
    } else {
        #pragma unroll
        for (int k = 0; k < 16; k++) {
            float4 v = *(const float4*)&stage[r*136 + h*64 + 4*k];
            *(float4*)&g_Vp[(size_t)(t0 + r) * 128 + h*64 + 4*k] = v;
        }
    }
}

// ---------------- kernel 2: scores (pipelined, stage overlays dead K) ------
// grid (80, 4). Q resident; K double-buffered; fp16 stage reuses current K buf.
// smem 102KB -> 2 CTAs/SM.
#define SCQ 0
#define SCK0 34816
#define SCK1 69632
#define SC_SMEM 104448

__global__ __launch_bounds__(256, 2) void scores_kernel() {
    extern __shared__ char smem[];
    const uint32_t sb = smem_u32(smem);
    const int tid = threadIdx.x;
    const int wid = tid >> 5, lane = tid & 31;
    const int grp = lane >> 2, qr = lane & 3;
    const int wm = wid >> 1, wn = wid & 1;
    const int b = blockIdx.y;

    int qt, g0, g1;
    decode_qt(blockIdx.x, qt, g0, g1);
    const int nk = g1 - g0;
    const int q0 = qt * 128;

    const char* Qsrc = (const char*)(g_Qs + (size_t)(b * Sc + q0) * 128);
    const char* Kbase = (const char*)(g_Ks + (size_t)b * Sc * 128);

    for (int idx = tid; idx < 2048; idx += 256) {
        int r = idx >> 4, ch = idx & 15;
        CP16(sb + SCQ + r*272 + ch*16, Qsrc + r*256 + ch*16);
        CP16(sb + SCK0 + r*272 + ch*16, Kbase + (size_t)(g0*128 + r)*256 + ch*16);
    }
    CP_COMMIT();

    const uint32_t aBase = sb + SCQ + (wm*32 + (lane & 15))*272 + (lane >> 4)*16;
    const uint32_t lmRow = (uint32_t)((wn*64 + (lane & 15))*272 + (lane >> 4)*16);
    const int aT[3] = {0, 1, 0}, bT[3] = {0, 0, 1};
    const float C = 0.18033688011112042f;   // 0.125 * log2(e)

    for (int i = 0; i < nk; i++) {
        const uint32_t kbuf = (i & 1) ? SCK1 : SCK0;
        if (i + 1 < nk) {
            const uint32_t nbuf = ((i + 1) & 1) ? SCK1 : SCK0;
            const size_t joff = (size_t)((g0 + i + 1) * 128) * 256;
            for (int idx = tid; idx < 2048; idx += 256) {
                int r = idx >> 4, ch = idx & 15;
                CP16(sb + nbuf + r*272 + ch*16, Kbase + joff + r*256 + ch*16);
            }
            CP_COMMIT();
            CP_WAITG(1);
        } else {
            CP_WAITG(0);
        }
        __syncthreads();

        float acc[2][8][4] = {};
        const uint32_t bBase = sb + kbuf + lmRow;
        #pragma unroll
        for (int t = 0; t < 3; t++) {
            #pragma unroll
            for (int ks = 0; ks < 4; ks++) {
                const uint32_t aOff = (uint32_t)(aT[t]*128 + ks*32);
                const uint32_t bOff = (uint32_t)(bT[t]*128 + ks*32);
                uint32_t afr[2][4];
                #pragma unroll
                for (int ma = 0; ma < 2; ma++)
                    LDM_X4(afr[ma][0], afr[ma][1], afr[ma][2], afr[ma][3],
                           aBase + ma*16*272 + aOff);
                uint32_t bfr[8][2];
                #pragma unroll
                for (int ng = 0; ng < 4; ng++) {
                    uint32_t d0, d1, d2, d3;
                    LDM_X4(d0, d1, d2, d3, bBase + ng*16*272 + bOff);
                    bfr[2*ng][0]   = d0; bfr[2*ng][1]   = d2;
                    bfr[2*ng+1][0] = d1; bfr[2*ng+1][1] = d3;
                }
                #pragma unroll
                for (int ma = 0; ma < 2; ma++)
                    #pragma unroll
                    for (int na = 0; na < 8; na++)
                        mma_bf16(acc[ma][na], afr[ma], bfr[na]);
            }
        }
        __syncthreads();   // K[i] dead everywhere; stage may overlay kbuf

        // epilogue: exp -> stage (overlaid on current K buffer, stride 272B)
        const int j0 = (g0 + i) * 128;
        __half* stage = (__half*)(smem + kbuf);   // [128][136]
        #pragma unroll
        for (int ma = 0; ma < 2; ma++) {
            const int r0 = wm*32 + ma*16 + grp;
            const int qlo = q0 + r0, qhi = qlo + 8;
            #pragma unroll
            for (int na = 0; na < 8; na++) {
                const int c0 = wn*64 + na*8 + qr*2;
                const int jc = j0 + c0;
                float t0 = (jc     <= qlo) ? acc[ma][na][0] * C : -1000.0f;
                float t1 = (jc + 1 <= qlo) ? acc[ma][na][1] * C : -1000.0f;
                float t2 = (jc     <= qhi) ? acc[ma][na][2] * C : -1000.0f;
                float t3 = (jc + 1 <= qhi) ? acc[ma][na][3] * C : -1000.0f;
                *(uint32_t*)&stage[r0*136 + c0]     = exp2h2(t0, t1);
                *(uint32_t*)&stage[(r0+8)*136 + c0] = exp2h2(t2, t3);
            }
        }
        __syncthreads();

        // E write + column sums
        {
            const int r = tid >> 1, h = tid & 1;
            const uint4* src = (const uint4*)((char*)stage + r*272 + h*128);
            uint4* dst = (uint4*)(g_E + (size_t)(b * Sc + q0 + r) * Sc + j0 + h*64);
            #pragma unroll
            for (int k = 0; k < 8; k++) dst[k] = src[k];
        }
        {
            const int col = tid & 127, rh = tid >> 7;
            float s = 0.0f;
            #pragma unroll 8
            for (int r = rh*64; r < rh*64 + 64; r++)
                s += __half2float(stage[r*136 + col]);
            atomicAdd(&g_denom[b * Sc + j0 + col], s);
        }
        __syncthreads();
    }
}

// ---------------- kernel 3: vprep ----------------
__global__ __launch_bounds__(256) void vprep_kernel() {
    __shared__ float tile[32][133];
    __shared__ float invs[32];
    const int b = blockIdx.y, s0 = blockIdx.x * 32, tid = threadIdx.x;
    if (tid < 32) invs[tid] = 1.0f / g_denom[b * Sc + s0 + tid];
    __syncthreads();
    #pragma unroll
    for (int i = 0; i < 16; i++) {
        int idx = tid + i * 256;
        int r = idx >> 7, c = idx & 127;
        tile[r][c] = g_Vp[(size_t)(b * Sc + s0 + r) * Vc + c] * invs[r];
    }
    __syncthreads();
    const int v = tid >> 1, h = tid & 1;
    uint32_t packs[8];
    #pragma unroll
    for (int k = 0; k < 8; k++)
        packs[k] = pack_h(__float2half(tile[h*16 + 2*k][v]),
                          __float2half(tile[h*16 + 2*k + 1][v]));
    uint4* dst = (uint4*)(g_Vt + (size_t)(b * Vc + v) * Sc + s0 + h*16);
    dst[0] = ((uint4*)packs)[0];
    dst[1] = ((uint4*)packs)[1];
}

// ---------------- kernel 4: concat ----------------
__global__ __launch_bounds__(256) void concat_kernel(const float* __restrict__ x,
                                                     float* __restrict__ out) {
    const int base = blockIdx.x * 256 + threadIdx.x;
    #pragma unroll
    for (int i = 0; i < 16; i++) {
        int idx = base + i * 65536;
        int c4 = idx & 63;
        int t = idx >> 6;
        float4 v = make_float4(0.f, 0.f, 0.f, 0.f);
        if (c4 < 32) v = ((const float4*)x)[(size_t)t * 32 + c4];
        ((float4*)out)[idx] = v;
    }
}

// ---------------- kernel 5: attn (single-buffer, 2 CTAs/SM) ----------------
#define AE 0
#define AV 34816
#define AT_SMEM 69632

__global__ __launch_bounds__(256, 2) void attn_kernel(float* __restrict__ out) {
    extern __shared__ char smem[];
    const uint32_t sb = smem_u32(smem);
    const int tid = threadIdx.x;
    const int wid = tid >> 5, lane = tid & 31;
    const int grp = lane >> 2, qr = lane & 3;
    const int wm = wid >> 1, wn = wid & 1;
    const int b = blockIdx.y;

    int qt, g0, g1;
    decode_qt(blockIdx.x, qt, g0, g1);
    const int nk = g1 - g0;
    const int q0 = qt * 128;

    const char* Ebase = (const char*)g_E + (size_t)(b*Sc + q0) * Sc * 2;
    const char* Vbase = (const char*)g_Vt + (size_t)b * Vc * Sc * 2;

    float acc[2][8][4] = {};
    const uint32_t lmA = (uint32_t)((wm*32 + (lane & 15))*272 + (lane >> 4)*16);
    const uint32_t lmB = (uint32_t)((wn*64 + (lane & 15))*272 + (lane >> 4)*16);
    const uint32_t aBase = sb + AE + lmA;
    const uint32_t bBase = sb + AV + lmB;

    for (int i = 0; i < nk; i++) {
        const int jcol = (g0 + i) * 256;
        for (int idx = tid; idx < 2048; idx += 256) {
            int r = idx >> 4, ch = idx & 15;
            CP16(sb + AE + r*272 + ch*16, Ebase + (size_t)r*Sc*2 + jcol + ch*16);
            CP16(sb + AV + r*272 + ch*16, Vbase + (size_t)r*Sc*2 + jcol + ch*16);
        }
        CP_COMMIT();
        CP_WAITG(0);
        __syncthreads();

        #pragma unroll
        for (int ks = 0; ks < 8; ks++) {
            const uint32_t kOff = (uint32_t)(ks * 32);
            uint32_t afr[2][4];
            #pragma unroll
            for (int ma = 0; ma < 2; ma++)
                LDM_X4(afr[ma][0], afr[ma][1], afr[ma][2], afr[ma][3],
                       aBase + ma*16*272 + kOff);
            uint32_t bfr[8][2];
            #pragma unroll
            for (int ng = 0; ng < 4; ng++) {
                uint32_t d0, d1, d2, d3;
                LDM_X4(d0, d1, d2, d3, bBase + ng*16*272 + kOff);
                bfr[2*ng][0]   = d0; bfr[2*ng][1]   = d2;
                bfr[2*ng+1][0] = d1; bfr[2*ng+1][1] = d3;
            }
            #pragma unroll
            for (int ma = 0; ma < 2; ma++)
                #pragma unroll
                for (int na = 0; na < 8; na++)
                    mma_f16(acc[ma][na], afr[ma], bfr[na]);
        }
        __syncthreads();
    }

    #pragma unroll
    for (int ma = 0; ma < 2; ma++) {
        const int r0 = q0 + wm*32 + ma*16 + grp;
        #pragma unroll
        for (int na = 0; na < 8; na++) {
            const int v0 = wn*64 + na*8 + qr*2;
            atomicAdd(&out[(size_t)(b*Sc + r0)*OUTC + Dc + v0],     acc[ma][na][0]);
            atomicAdd(&out[(size_t)(b*Sc + r0)*OUTC + Dc + v0 + 1], acc[ma][na][1]);
            atomicAdd(&out[(size_t)(b*Sc + r0 + 8)*OUTC + Dc + v0],     acc[ma][na][2]);
            atomicAdd(&out[(size_t)(b*Sc + r0 + 8)*OUTC + Dc + v0 + 1], acc[ma][na][3]);
        }
    }
}

// ---------------- launch ----------------
extern "C" void kernel_launch(void* const* d_in, const int* in_sizes, int n_in,
                              void* d_out, int out_size) {
    const float* x  = (const float*)d_in[0];
    const float* Wq = (const float*)d_in[1];
    const float* bq = (const float*)d_in[2];
    const float* Wk = (const float*)d_in[3];
    const float* bk = (const float*)d_in[4];
    const float* Wv = (const float*)d_in[5];
    const float* bv = (const float*)d_in[6];
    float* out = (float*)d_out;

    cudaFuncSetAttribute(proj_kernel,   cudaFuncAttributeMaxDynamicSharedMemorySize, PJ_SMEM);
    cudaFuncSetAttribute(scores_kernel, cudaFuncAttributeMaxDynamicSharedMemorySize, SC_SMEM);
    cudaFuncSetAttribute(attn_kernel,   cudaFuncAttributeMaxDynamicSharedMemorySize, AT_SMEM);

    proj_kernel<<<dim3(BSc / 128, 2), 256, PJ_SMEM>>>(x, Wq, bq, Wk, bk, Wv, bv);
    scores_kernel<<<dim3(80, Bc), 256, SC_SMEM>>>();
    vprep_kernel<<<dim3(Sc / 32, Bc), 256>>>();
    concat_kernel<<<256, 256>>>(x, out);
    attn_kernel<<<dim3(80, Bc), 256, AT_SMEM>>>(out);
}

// round 11
// speedup vs baseline: 1.1387x; 1.1152x over previous
#include <cuda_runtime.h>
#include <cuda_bf16.h>
#include <cuda_fp16.h>
#include <cstdint>

#define Bc 4
#define Sc 4096
#define Dc 128
#define Kc 64
#define Vc 128
#define BSc (Bc*Sc)
#define OUTC 256

// ---------------- scratch ----------------
__device__ __nv_bfloat16 g_Qs[(size_t)BSc * 128];      // [hi64 | lo64] per token
__device__ __nv_bfloat16 g_Ks[(size_t)BSc * 128];
__device__ float         g_Vp[(size_t)BSc * Vc];
__device__ __half        g_E[(size_t)Bc * Sc * Sc];    // exp(scores), causal zeros
__device__ __half        g_Vt[(size_t)Bc * Vc * Sc];   // [b][v][s], V/denom, fp16
__device__ float         g_denom[BSc];

// ---------------- PTX helpers ----------------
__device__ __forceinline__ uint32_t smem_u32(const void* p) {
    uint32_t a;
    asm("{ .reg .u64 t; cvta.to.shared.u64 t, %1; cvt.u32.u64 %0, t; }" : "=r"(a) : "l"(p));
    return a;
}
#define CP16(dst, src) \
    asm volatile("cp.async.cg.shared.global [%0], [%1], 16;" :: "r"(dst), "l"(src))
#define CP_COMMIT() asm volatile("cp.async.commit_group;" ::: "memory")
#define CP_WAITG(n) asm volatile("cp.async.wait_group %0;" :: "n"(n) : "memory")
#define LDM_X4(d0, d1, d2, d3, a) \
    asm volatile("ldmatrix.sync.aligned.m8n8.x4.shared.b16 {%0,%1,%2,%3}, [%4];" \
        : "=r"(d0), "=r"(d1), "=r"(d2), "=r"(d3) : "r"(a))

__device__ __forceinline__ void mma_bf16(float* d, const uint32_t* a, const uint32_t* b) {
    asm volatile("mma.sync.aligned.m16n8k16.row.col.f32.bf16.bf16.f32 "
        "{%0,%1,%2,%3}, {%4,%5,%6,%7}, {%8,%9}, {%0,%1,%2,%3};"
        : "+f"(d[0]), "+f"(d[1]), "+f"(d[2]), "+f"(d[3])
        : "r"(a[0]), "r"(a[1]), "r"(a[2]), "r"(a[3]), "r"(b[0]), "r"(b[1]));
}
__device__ __forceinline__ void mma_f16(float* d, const uint32_t* a, const uint32_t* b) {
    asm volatile("mma.sync.aligned.m16n8k16.row.col.f32.f16.f16.f32 "
        "{%0,%1,%2,%3}, {%4,%5,%6,%7}, {%8,%9}, {%0,%1,%2,%3};"
        : "+f"(d[0]), "+f"(d[1]), "+f"(d[2]), "+f"(d[3])
        : "r"(a[0]), "r"(a[1]), "r"(a[2]), "r"(a[3]), "r"(b[0]), "r"(b[1]));
}
__device__ __forceinline__ uint32_t pack_h(__half a, __half b) {
    __half2 t; t.x = a; t.y = b;
    return *reinterpret_cast<uint32_t*>(&t);
}
__device__ __forceinline__ uint32_t pack_b(__nv_bfloat16 a, __nv_bfloat16 b) {
    __nv_bfloat162 t; t.x = a; t.y = b;
    return *reinterpret_cast<uint32_t*>(&t);
}

// exp(s/8) as 2^(s*C): ex2.approx.f16x2 + fp32 residual correction.
__device__ __forceinline__ uint32_t exp2h2(float t0, float t1) {
    __half2 th = __floats2half2_rn(t0, t1);
    uint32_t thu = *reinterpret_cast<uint32_t*>(&th);
    uint32_t eu;
    asm("ex2.approx.f16x2 %0, %1;" : "=r"(eu) : "r"(thu));
    float tl0 = t0 - __half2float(__low2half(th));
    float tl1 = t1 - __half2float(__high2half(th));
    __half2 c = __floats2half2_rn(fmaf(0.6931472f, tl0, 1.0f),
                                  fmaf(0.6931472f, tl1, 1.0f));
    __half2 e = *reinterpret_cast<__half2*>(&eu);
    e = __hmul2(e, c);
    return *reinterpret_cast<uint32_t*>(&e);
}

// causal (qt, group-of-8) decode, heaviest first; sum over qt of ceil((qt+1)/8) = 80
__device__ __forceinline__ void decode_qt(int bx, int& qt, int& g0, int& g1) {
    int lin = 79 - bx;
    int base = 0; qt = 0;
    for (;;) { int gq = (qt + 8) >> 3; if (lin < base + gq) break; base += gq; qt++; }
    g0 = (lin - base) * 8;
    g1 = min(qt + 1, g0 + 8);
}

// ---------------- kernel 1: projections (mma split-bf16) -------------------
// nh==0 CTAs also write out[:, :128] = x and zero out[:, 128:256].
#define PJ_A0 0
#define PJ_A1 34816
#define PJ_B0 69632
#define PJ_B1 104448
#define PJ_BIAS 139264
#define PJ_SMEM 139776

__global__ __launch_bounds__(256) void proj_kernel(
    const float* __restrict__ x,
    const float* __restrict__ Wq, const float* __restrict__ bq,
    const float* __restrict__ Wk, const float* __restrict__ bk,
    const float* __restrict__ Wv, const float* __restrict__ bv,
    float* __restrict__ out) {
    extern __shared__ char smem[];
    const uint32_t sb = smem_u32(smem);
    const int tid = threadIdx.x;
    const int wid = tid >> 5, lane = tid & 31;
    const int grp = lane >> 2, qr = lane & 3;
    const int wm = wid >> 1, wn = wid & 1;
    const int nh = blockIdx.y;
    const int t0 = blockIdx.x * 128;

    if (nh == 0) {
        int i = blockIdx.x * 256 + tid;
        if (i < BSc) g_denom[i] = 0.0f;
    }
    if (tid < 128) {
        float bvv = (nh == 0) ? ((tid < 64) ? bq[tid] : bk[tid - 64]) : bv[tid];
        ((float*)(smem + PJ_BIAS))[tid] = bvv;
    }

    #pragma unroll
    for (int i = 0; i < 16; i++) {
        int idx = tid + i * 256;
        int r = idx >> 5, c4 = idx & 31;
        int ch = c4 >> 4, cc = c4 & 15;
        float4 a = *(const float4*)&x[(size_t)(t0 + r) * 128 + c4 * 4];
        if (nh == 0) {   // fused concat: out[:, :128] = x, out[:, 128:] = 0
            ((float4*)out)[(size_t)(t0 + r) * 64 + c4] = a;
            ((float4*)out)[(size_t)(t0 + r) * 64 + 32 + c4] =
                make_float4(0.f, 0.f, 0.f, 0.f);
        }
        __nv_bfloat16 h0 = __float2bfloat16(a.x), h1 = __float2bfloat16(a.y);
        __nv_bfloat16 h2 = __float2bfloat16(a.z), h3 = __float2bfloat16(a.w);
        uint2 hi = make_uint2(pack_b(h0, h1), pack_b(h2, h3));
        uint2 lo = make_uint2(
            pack_b(__float2bfloat16(a.x - __bfloat162float(h0)),
                   __float2bfloat16(a.y - __bfloat162float(h1))),
            pack_b(__float2bfloat16(a.z - __bfloat162float(h2)),
                   __float2bfloat16(a.w - __bfloat162float(h3))));
        char* ab = smem + (ch ? PJ_A1 : PJ_A0) + r * 272 + cc * 8;
        *(uint2*)ab = hi;
        *(uint2*)(ab + 128) = lo;

        const float* wsrc = (nh == 0)
            ? ((r < 64) ? (Wq + (size_t)r * 128) : (Wk + (size_t)(r - 64) * 128))
            : (Wv + (size_t)r * 128);
        float4 w = *(const float4*)&wsrc[c4 * 4];
        __nv_bfloat16 g0 = __float2bfloat16(w.x), g1 = __float2bfloat16(w.y);
        __nv_bfloat16 g2 = __float2bfloat16(w.z), g3 = __float2bfloat16(w.w);
        uint2 whi = make_uint2(pack_b(g0, g1), pack_b(g2, g3));
        uint2 wlo = make_uint2(
            pack_b(__float2bfloat16(w.x - __bfloat162float(g0)),
                   __float2bfloat16(w.y - __bfloat162float(g1))),
            pack_b(__float2bfloat16(w.z - __bfloat162float(g2)),
                   __float2bfloat16(w.w - __bfloat162float(g3))));
        char* bb = smem + (ch ? PJ_B1 : PJ_B0) + r * 272 + cc * 8;
        *(uint2*)bb = whi;
        *(uint2*)(bb + 128) = wlo;
    }
    __syncthreads();

    float acc[2][8][4] = {};
    const uint32_t aBase = sb + PJ_A0 + (wm*32 + (lane & 15))*272 + (lane >> 4)*16;
    const uint32_t bBase = sb + PJ_B0 + (wn*64 + (lane & 15))*272 + (lane >> 4)*16;
    const int aT[3] = {0, 1, 0}, bT[3] = {0, 0, 1};

    #pragma unroll
    for (int ch = 0; ch < 2; ch++) {
        #pragma unroll
        for (int t = 0; t < 3; t++) {
            #pragma unroll
            for (int ks = 0; ks < 4; ks++) {
                const uint32_t aOff = (uint32_t)(ch*34816 + aT[t]*128 + ks*32);
                const uint32_t bOff = (uint32_t)(ch*34816 + bT[t]*128 + ks*32);
                uint32_t afr[2][4];
                #pragma unroll
                for (int ma = 0; ma < 2; ma++)
                    LDM_X4(afr[ma][0], afr[ma][1], afr[ma][2], afr[ma][3],
                           aBase + ma*16*272 + aOff);
                uint32_t bfr[8][2];
                #pragma unroll
                for (int ng = 0; ng < 4; ng++) {
                    uint32_t d0, d1, d2, d3;
                    LDM_X4(d0, d1, d2, d3, bBase + ng*16*272 + bOff);
                    bfr[2*ng][0]   = d0; bfr[2*ng][1]   = d2;
                    bfr[2*ng+1][0] = d1; bfr[2*ng+1][1] = d3;
                }
                #pragma unroll
                for (int ma = 0; ma < 2; ma++)
                    #pragma unroll
                    for (int na = 0; na < 8; na++)
                        mma_bf16(acc[ma][na], afr[ma], bfr[na]);
            }
        }
    }
    __syncthreads();

    float* stage = (float*)smem;                 // [128][136]
    const float* biasS = (const float*)(smem + PJ_BIAS);
    #pragma unroll
    for (int ma = 0; ma < 2; ma++) {
        const int r0 = wm*32 + ma*16 + grp;
        #pragma unroll
        for (int na = 0; na < 8; na++) {
            const int c0 = wn*64 + na*8 + qr*2;
            stage[r0*136 + c0]     = acc[ma][na][0] + biasS[c0];
            stage[r0*136 + c0 + 1] = acc[ma][na][1] + biasS[c0 + 1];
            stage[(r0+8)*136 + c0]     = acc[ma][na][2] + biasS[c0];
            stage[(r0+8)*136 + c0 + 1] = acc[ma][na][3] + biasS[c0 + 1];
        }
    }
    __syncthreads();

    const int r = tid >> 1, h = tid & 1;
    if (nh == 0) {
        uint32_t hp[32], lp[32];
        #pragma unroll
        for (int k = 0; k < 32; k++) {
            float v0 = stage[r*136 + h*64 + 2*k];
            float v1 = stage[r*136 + h*64 + 2*k + 1];
            __nv_bfloat16 b0 = __float2bfloat16(v0), b1 = __float2bfloat16(v1);
            hp[k] = pack_b(b0, b1);
            lp[k] = pack_b(__float2bfloat16(v0 - __bfloat162float(b0)),
                           __float2bfloat16(v1 - __bfloat162float(b1)));
        }
        __nv_bfloat16* dstrow = (h == 0 ? g_Qs : g_Ks) + (size_t)(t0 + r) * 128;
        uint4* dh = (uint4*)dstrow;
        uint4* dl = (uint4*)(dstrow + 64);
        #pragma unroll
        for (int k = 0; k < 8; k++) { dh[k] = ((uint4*)hp)[k]; dl[k] = ((uint4*)lp)[k]; }
    } else {
        #pragma unroll
        for (int k = 0; k < 16; k++) {
            float4 v = *(const float4*)&stage[r*136 + h*64 + 4*k];
            *(float4*)&g_Vp[(size_t)(t0 + r) * 128 + h*64 + 4*k] = v;
        }
    }
}

// ---------------- kernel 2: scores (R8 pipeline + register colsum) ---------
#define SCQ 0
#define SCK0 34816
#define SCK1 69632
#define SCST 104448
#define SC_SMEM 139264

__global__ __launch_bounds__(256) void scores_kernel() {
    extern __shared__ char smem[];
    const uint32_t sb = smem_u32(smem);
    const int tid = threadIdx.x;
    const int wid = tid >> 5, lane = tid & 31;
    const int grp = lane >> 2, qr = lane & 3;
    const int wm = wid >> 1, wn = wid & 1;
    const int b = blockIdx.y;

    int qt, g0, g1;
    decode_qt(blockIdx.x, qt, g0, g1);
    const int nk = g1 - g0;
    const int q0 = qt * 128;

    const char* Qsrc = (const char*)(g_Qs + (size_t)(b * Sc + q0) * 128);
    const char* Kbase = (const char*)(g_Ks + (size_t)b * Sc * 128);

    for (int idx = tid; idx < 2048; idx += 256) {
        int r = idx >> 4, ch = idx & 15;
        CP16(sb + SCQ + r*272 + ch*16, Qsrc + r*256 + ch*16);
        CP16(sb + SCK0 + r*272 + ch*16, Kbase + (size_t)(g0*128 + r)*256 + ch*16);
    }
    CP_COMMIT();

    const uint32_t aBase = sb + SCQ + (wm*32 + (lane & 15))*272 + (lane >> 4)*16;
    const uint32_t lmRow = (uint32_t)((wn*64 + (lane & 15))*272 + (lane >> 4)*16);
    const int aT[3] = {0, 1, 0}, bT[3] = {0, 0, 1};
    const float C = 0.18033688011112042f;   // 0.125 * log2(e)
    __half* stage = (__half*)(smem + SCST); // [128][136]

    for (int i = 0; i < nk; i++) {
        const uint32_t kbuf = (i & 1) ? SCK1 : SCK0;
        if (i + 1 < nk) {
            const uint32_t nbuf = ((i + 1) & 1) ? SCK1 : SCK0;
            const size_t joff = (size_t)((g0 + i + 1) * 128) * 256;
            for (int idx = tid; idx < 2048; idx += 256) {
                int r = idx >> 4, ch = idx & 15;
                CP16(sb + nbuf + r*272 + ch*16, Kbase + joff + r*256 + ch*16);
            }
            CP_COMMIT();
            CP_WAITG(1);
        } else {
            CP_WAITG(0);
        }
        __syncthreads();

        float acc[2][8][4] = {};
        const uint32_t bBase = sb + kbuf + lmRow;
        #pragma unroll
        for (int t = 0; t < 3; t++) {
            #pragma unroll
            for (int ks = 0; ks < 4; ks++) {
                const uint32_t aOff = (uint32_t)(aT[t]*128 + ks*32);
                const uint32_t bOff = (uint32_t)(bT[t]*128 + ks*32);
                uint32_t afr[2][4];
                #pragma unroll
                for (int ma = 0; ma < 2; ma++)
                    LDM_X4(afr[ma][0], afr[ma][1], afr[ma][2], afr[ma][3],
                           aBase + ma*16*272 + aOff);
                uint32_t bfr[8][2];
                #pragma unroll
                for (int ng = 0; ng < 4; ng++) {
                    uint32_t d0, d1, d2, d3;
                    LDM_X4(d0, d1, d2, d3, bBase + ng*16*272 + bOff);
                    bfr[2*ng][0]   = d0; bfr[2*ng][1]   = d2;
                    bfr[2*ng+1][0] = d1; bfr[2*ng+1][1] = d3;
                }
                #pragma unroll
                for (int ma = 0; ma < 2; ma++)
                    #pragma unroll
                    for (int na = 0; na < 8; na++)
                        mma_bf16(acc[ma][na], afr[ma], bfr[na]);
            }
        }

        // epilogue: exp -> stage + in-register column sums (R9-proven)
        const int j0 = (g0 + i) * 128;
        float cs0[8] = {}, cs1[8] = {};
        #pragma unroll
        for (int ma = 0; ma < 2; ma++) {
            const int r0 = wm*32 + ma*16 + grp;
            const int qlo = q0 + r0, qhi = qlo + 8;
            #pragma unroll
            for (int na = 0; na < 8; na++) {
                const int c0 = wn*64 + na*8 + qr*2;
                const int jc = j0 + c0;
                float t0 = (jc     <= qlo) ? acc[ma][na][0] * C : -1000.0f;
                float t1 = (jc + 1 <= qlo) ? acc[ma][na][1] * C : -1000.0f;
                float t2 = (jc     <= qhi) ? acc[ma][na][2] * C : -1000.0f;
                float t3 = (jc + 1 <= qhi) ? acc[ma][na][3] * C : -1000.0f;
                uint32_t u0 = exp2h2(t0, t1), u1 = exp2h2(t2, t3);
                *(uint32_t*)&stage[r0*136 + c0]     = u0;
                *(uint32_t*)&stage[(r0+8)*136 + c0] = u1;
                __half2 e0 = *reinterpret_cast<__half2*>(&u0);
                __half2 e1 = *reinterpret_cast<__half2*>(&u1);
                cs0[na] += __low2float(e0)  + __low2float(e1);
                cs1[na] += __high2float(e0) + __high2float(e1);
            }
        }
        // reduce over row lanes (grp bits) then atomic add
        #pragma unroll
        for (int na = 0; na < 8; na++) {
            #pragma unroll
            for (int m = 4; m <= 16; m <<= 1) {
                cs0[na] += __shfl_xor_sync(0xFFFFFFFFu, cs0[na], m);
                cs1[na] += __shfl_xor_sync(0xFFFFFFFFu, cs1[na], m);
            }
        }
        if (grp == 0) {
            #pragma unroll
            for (int na = 0; na < 8; na++) {
                const int jc = j0 + wn*64 + na*8 + qr*2;
                atomicAdd(&g_denom[b * Sc + jc],     cs0[na]);
                atomicAdd(&g_denom[b * Sc + jc + 1], cs1[na]);
            }
        }
        __syncthreads();

        // E write (coalesced uint4) from stage
        {
            const int r = tid >> 1, h = tid & 1;
            const uint4* src = (const uint4*)((char*)stage + r*272 + h*128);
            uint4* dst = (uint4*)(g_E + (size_t)(b * Sc + q0 + r) * Sc + j0 + h*64);
            #pragma unroll
            for (int k = 0; k < 8; k++) dst[k] = src[k];
        }
        __syncthreads();
    }
}

// ---------------- kernel 3: vprep ----------------
__global__ __launch_bounds__(256) void vprep_kernel() {
    __shared__ float tile[32][133];
    __shared__ float invs[32];
    const int b = blockIdx.y, s0 = blockIdx.x * 32, tid = threadIdx.x;
    if (tid < 32) invs[tid] = 1.0f / g_denom[b * Sc + s0 + tid];
    __syncthreads();
    #pragma unroll
    for (int i = 0; i < 16; i++) {
        int idx = tid + i * 256;
        int r = idx >> 7, c = idx & 127;
        tile[r][c] = g_Vp[(size_t)(b * Sc + s0 + r) * Vc + c] * invs[r];
    }
    __syncthreads();
    const int v = tid >> 1, h = tid & 1;
    uint32_t packs[8];
    #pragma unroll
    for (int k = 0; k < 8; k++)
        packs[k] = pack_h(__float2half(tile[h*16 + 2*k][v]),
                          __float2half(tile[h*16 + 2*k + 1][v]));
    uint4* dst = (uint4*)(g_Vt + (size_t)(b * Vc + v) * Sc + s0 + h*16);
    dst[0] = ((uint4*)packs)[0];
    dst[1] = ((uint4*)packs)[1];
}

// ---------------- kernel 4: attn (R8 pipelined double-buffer) --------------
#define AE0 0
#define AV0 34816
#define AE1 69632
#define AV1 104448
#define AT_SMEM 139264

__global__ __launch_bounds__(256) void attn_kernel(float* __restrict__ out) {
    extern __shared__ char smem[];
    const uint32_t sb = smem_u32(smem);
    const int tid = threadIdx.x;
    const int wid = tid >> 5, lane = tid & 31;
    const int grp = lane >> 2, qr = lane & 3;
    const int wm = wid >> 1, wn = wid & 1;
    const int b = blockIdx.y;

    int qt, g0, g1;
    decode_qt(blockIdx.x, qt, g0, g1);
    const int nk = g1 - g0;
    const int q0 = qt * 128;

    const char* Ebase = (const char*)g_E + (size_t)(b*Sc + q0) * Sc * 2;
    const char* Vbase = (const char*)g_Vt + (size_t)b * Vc * Sc * 2;

    for (int idx = tid; idx < 2048; idx += 256) {
        int r = idx >> 4, ch = idx & 15;
        CP16(sb + AE0 + r*272 + ch*16, Ebase + (size_t)r*Sc*2 + g0*256 + ch*16);
        CP16(sb + AV0 + r*272 + ch*16, Vbase + (size_t)r*Sc*2 + g0*256 + ch*16);
    }
    CP_COMMIT();

    float acc[2][8][4] = {};
    const uint32_t lmA = (uint32_t)((wm*32 + (lane & 15))*272 + (lane >> 4)*16);
    const uint32_t lmB = (uint32_t)((wn*64 + (lane & 15))*272 + (lane >> 4)*16);

    for (int i = 0; i < nk; i++) {
        const uint32_t ebuf = (i & 1) ? AE1 : AE0;
        const uint32_t vbuf = (i & 1) ? AV1 : AV0;
        if (i + 1 < nk) {
            const uint32_t ne = ((i + 1) & 1) ? AE1 : AE0;
            const uint32_t nv = ((i + 1) & 1) ? AV1 : AV0;
            const int jcol = (g0 + i + 1) * 256;
            for (int idx = tid; idx < 2048; idx += 256) {
                int r = idx >> 4, ch = idx & 15;
                CP16(sb + ne + r*272 + ch*16, Ebase + (size_t)r*Sc*2 + jcol + ch*16);
                CP16(sb + nv + r*272 + ch*16, Vbase + (size_t)r*Sc*2 + jcol + ch*16);
            }
            CP_COMMIT();
            CP_WAITG(1);
        } else {
            CP_WAITG(0);
        }
        __syncthreads();

        const uint32_t aBase = sb + ebuf + lmA;
        const uint32_t bBase = sb + vbuf + lmB;
        #pragma unroll
        for (int ks = 0; ks < 8; ks++) {
            const uint32_t kOff = (uint32_t)(ks * 32);
            uint32_t afr[2][4];
            #pragma unroll
            for (int ma = 0; ma < 2; ma++)
                LDM_X4(afr[ma][0], afr[ma][1], afr[ma][2], afr[ma][3],
                       aBase + ma*16*272 + kOff);
            uint32_t bfr[8][2];
            #pragma unroll
            for (int ng = 0; ng < 4; ng++) {
                uint32_t d0, d1, d2, d3;
                LDM_X4(d0, d1, d2, d3, bBase + ng*16*272 + kOff);
                bfr[2*ng][0]   = d0; bfr[2*ng][1]   = d2;
                bfr[2*ng+1][0] = d1; bfr[2*ng+1][1] = d3;
            }
            #pragma unroll
            for (int ma = 0; ma < 2; ma++)
                #pragma unroll
                for (int na = 0; na < 8; na++)
                    mma_f16(acc[ma][na], afr[ma], bfr[na]);
        }
        __syncthreads();
    }

    #pragma unroll
    for (int ma = 0; ma < 2; ma++) {
        const int r0 = q0 + wm*32 + ma*16 + grp;
        #pragma unroll
        for (int na = 0; na < 8; na++) {
            const int v0 = wn*64 + na*8 + qr*2;
            atomicAdd(&out[(size_t)(b*Sc + r0)*OUTC + Dc + v0],     acc[ma][na][0]);
            atomicAdd(&out[(size_t)(b*Sc + r0)*OUTC + Dc + v0 + 1], acc[ma][na][1]);
            atomicAdd(&out[(size_t)(b*Sc + r0 + 8)*OUTC + Dc + v0],     acc[ma][na][2]);
            atomicAdd(&out[(size_t)(b*Sc + r0 + 8)*OUTC + Dc + v0 + 1], acc[ma][na][3]);
        }
    }
}

// ---------------- launch ----------------
extern "C" void kernel_launch(void* const* d_in, const int* in_sizes, int n_in,
                              void* d_out, int out_size) {
    const float* x  = (const float*)d_in[0];
    const float* Wq = (const float*)d_in[1];
    const float* bq = (const float*)d_in[2];
    const float* Wk = (const float*)d_in[3];
    const float* bk = (const float*)d_in[4];
    const float* Wv = (const float*)d_in[5];
    const float* bv = (const float*)d_in[6];
    float* out = (float*)d_out;

    cudaFuncSetAttribute(proj_kernel,   cudaFuncAttributeMaxDynamicSharedMemorySize, PJ_SMEM);
    cudaFuncSetAttribute(scores_kernel, cudaFuncAttributeMaxDynamicSharedMemorySize, SC_SMEM);
    cudaFuncSetAttribute(attn_kernel,   cudaFuncAttributeMaxDynamicSharedMemorySize, AT_SMEM);

    proj_kernel<<<dim3(BSc / 128, 2), 256, PJ_SMEM>>>(x, Wq, bq, Wk, bk, Wv, bv, out);
    scores_kernel<<<dim3(80, Bc), 256, SC_SMEM>>>();
    vprep_kernel<<<dim3(Sc / 32, Bc), 256>>>();
    attn_kernel<<<dim3(80, Bc), 256, AT_SMEM>>>(out);
}

// round 12
// speedup vs baseline: 1.2111x; 1.0636x over previous
#include <cuda_runtime.h>
#include <cuda_bf16.h>
#include <cuda_fp16.h>
#include <cstdint>

#define Bc 4
#define Sc 4096
#define Dc 128
#define Kc 64
#define Vc 128
#define BSc (Bc*Sc)
#define OUTC 256

// ---------------- scratch ----------------
__device__ __nv_bfloat16 g_Qs[(size_t)BSc * 128];      // [hi64 | lo64] per token
__device__ __nv_bfloat16 g_Ks[(size_t)BSc * 128];
__device__ float         g_Vp[(size_t)BSc * Vc];
__device__ __half        g_E[(size_t)Bc * Sc * Sc];    // exp(scores), causal zeros
__device__ __half        g_Vt[(size_t)Bc * Vc * Sc];   // [b][v][s], V/denom, fp16
__device__ float         g_denom[BSc];

// ---------------- PTX helpers ----------------
__device__ __forceinline__ uint32_t smem_u32(const void* p) {
    uint32_t a;
    asm("{ .reg .u64 t; cvta.to.shared.u64 t, %1; cvt.u32.u64 %0, t; }" : "=r"(a) : "l"(p));
    return a;
}
#define CP16(dst, src) \
    asm volatile("cp.async.cg.shared.global [%0], [%1], 16;" :: "r"(dst), "l"(src))
#define CP_COMMIT() asm volatile("cp.async.commit_group;" ::: "memory")
#define CP_WAITG(n) asm volatile("cp.async.wait_group %0;" :: "n"(n) : "memory")
#define LDM_X4(d0, d1, d2, d3, a) \
    asm volatile("ldmatrix.sync.aligned.m8n8.x4.shared.b16 {%0,%1,%2,%3}, [%4];" \
        : "=r"(d0), "=r"(d1), "=r"(d2), "=r"(d3) : "r"(a))

__device__ __forceinline__ void mma_bf16(float* d, const uint32_t* a, const uint32_t* b) {
    asm volatile("mma.sync.aligned.m16n8k16.row.col.f32.bf16.bf16.f32 "
        "{%0,%1,%2,%3}, {%4,%5,%6,%7}, {%8,%9}, {%0,%1,%2,%3};"
        : "+f"(d[0]), "+f"(d[1]), "+f"(d[2]), "+f"(d[3])
        : "r"(a[0]), "r"(a[1]), "r"(a[2]), "r"(a[3]), "r"(b[0]), "r"(b[1]));
}
__device__ __forceinline__ void mma_f16(float* d, const uint32_t* a, const uint32_t* b) {
    asm volatile("mma.sync.aligned.m16n8k16.row.col.f32.f16.f16.f32 "
        "{%0,%1,%2,%3}, {%4,%5,%6,%7}, {%8,%9}, {%0,%1,%2,%3};"
        : "+f"(d[0]), "+f"(d[1]), "+f"(d[2]), "+f"(d[3])
        : "r"(a[0]), "r"(a[1]), "r"(a[2]), "r"(a[3]), "r"(b[0]), "r"(b[1]));
}
__device__ __forceinline__ uint32_t pack_h(__half a, __half b) {
    __half2 t; t.x = a; t.y = b;
    return *reinterpret_cast<uint32_t*>(&t);
}
__device__ __forceinline__ uint32_t pack_b(__nv_bfloat16 a, __nv_bfloat16 b) {
    __nv_bfloat162 t; t.x = a; t.y = b;
    return *reinterpret_cast<uint32_t*>(&t);
}

// exp(s/8) as 2^(s*C): ex2.approx.f16x2 + fp32 residual correction.
__device__ __forceinline__ uint32_t exp2h2(float t0, float t1) {
    __half2 th = __floats2half2_rn(t0, t1);
    uint32_t thu = *reinterpret_cast<uint32_t*>(&th);
    uint32_t eu;
    asm("ex2.approx.f16x2 %0, %1;" : "=r"(eu) : "r"(thu));
    float tl0 = t0 - __half2float(__low2half(th));
    float tl1 = t1 - __half2float(__high2half(th));
    __half2 c = __floats2half2_rn(fmaf(0.6931472f, tl0, 1.0f),
                                  fmaf(0.6931472f, tl1, 1.0f));
    __half2 e = *reinterpret_cast<__half2*>(&eu);
    e = __hmul2(e, c);
    return *reinterpret_cast<uint32_t*>(&e);
}

// causal (qt, group-of-8) decode, heaviest first; sum over qt of ceil((qt+1)/8) = 80
__device__ __forceinline__ void decode_qt(int bx, int& qt, int& g0, int& g1) {
    int lin = 79 - bx;
    int base = 0; qt = 0;
    for (;;) { int gq = (qt + 8) >> 3; if (lin < base + gq) break; base += gq; qt++; }
    g0 = (lin - base) * 8;
    g1 = min(qt + 1, g0 + 8);
}

// ---------------- kernel 1: projections (mma split-bf16) -------------------
// nh==0 CTAs also write out[:, :128] = x and zero out[:, 128:256].
#define PJ_A0 0
#define PJ_A1 34816
#define PJ_B0 69632
#define PJ_B1 104448
#define PJ_BIAS 139264
#define PJ_SMEM 139776

__global__ __launch_bounds__(256) void proj_kernel(
    const float* __restrict__ x,
    const float* __restrict__ Wq, const float* __restrict__ bq,
    const float* __restrict__ Wk, const float* __restrict__ bk,
    const float* __restrict__ Wv, const float* __restrict__ bv,
    float* __restrict__ out) {
    extern __shared__ char smem[];
    const uint32_t sb = smem_u32(smem);
    const int tid = threadIdx.x;
    const int wid = tid >> 5, lane = tid & 31;
    const int grp = lane >> 2, qr = lane & 3;
    const int wm = wid >> 1, wn = wid & 1;
    const int nh = blockIdx.y;
    const int t0 = blockIdx.x * 128;

    if (nh == 0) {
        int i = blockIdx.x * 256 + tid;
        if (i < BSc) g_denom[i] = 0.0f;
    }
    if (tid < 128) {
        float bvv = (nh == 0) ? ((tid < 64) ? bq[tid] : bk[tid - 64]) : bv[tid];
        ((float*)(smem + PJ_BIAS))[tid] = bvv;
    }

    #pragma unroll
    for (int i = 0; i < 16; i++) {
        int idx = tid + i * 256;
        int r = idx >> 5, c4 = idx & 31;
        int ch = c4 >> 4, cc = c4 & 15;
        float4 a = *(const float4*)&x[(size_t)(t0 + r) * 128 + c4 * 4];
        if (nh == 0) {   // fused concat: out[:, :128] = x, out[:, 128:] = 0
            ((float4*)out)[(size_t)(t0 + r) * 64 + c4] = a;
            ((float4*)out)[(size_t)(t0 + r) * 64 + 32 + c4] =
                make_float4(0.f, 0.f, 0.f, 0.f);
        }
        __nv_bfloat16 h0 = __float2bfloat16(a.x), h1 = __float2bfloat16(a.y);
        __nv_bfloat16 h2 = __float2bfloat16(a.z), h3 = __float2bfloat16(a.w);
        uint2 hi = make_uint2(pack_b(h0, h1), pack_b(h2, h3));
        uint2 lo = make_uint2(
            pack_b(__float2bfloat16(a.x - __bfloat162float(h0)),
                   __float2bfloat16(a.y - __bfloat162float(h1))),
            pack_b(__float2bfloat16(a.z - __bfloat162float(h2)),
                   __float2bfloat16(a.w - __bfloat162float(h3))));
        char* ab = smem + (ch ? PJ_A1 : PJ_A0) + r * 272 + cc * 8;
        *(uint2*)ab = hi;
        *(uint2*)(ab + 128) = lo;

        const float* wsrc = (nh == 0)
            ? ((r < 64) ? (Wq + (size_t)r * 128) : (Wk + (size_t)(r - 64) * 128))
            : (Wv + (size_t)r * 128);
        float4 w = *(const float4*)&wsrc[c4 * 4];
        __nv_bfloat16 g0 = __float2bfloat16(w.x), g1 = __float2bfloat16(w.y);
        __nv_bfloat16 g2 = __float2bfloat16(w.z), g3 = __float2bfloat16(w.w);
        uint2 whi = make_uint2(pack_b(g0, g1), pack_b(g2, g3));
        uint2 wlo = make_uint2(
            pack_b(__float2bfloat16(w.x - __bfloat162float(g0)),
                   __float2bfloat16(w.y - __bfloat162float(g1))),
            pack_b(__float2bfloat16(w.z - __bfloat162float(g2)),
                   __float2bfloat16(w.w - __bfloat162float(g3))));
        char* bb = smem + (ch ? PJ_B1 : PJ_B0) + r * 272 + cc * 8;
        *(uint2*)bb = whi;
        *(uint2*)(bb + 128) = wlo;
    }
    __syncthreads();

    float acc[2][8][4] = {};
    const uint32_t aBase = sb + PJ_A0 + (wm*32 + (lane & 15))*272 + (lane >> 4)*16;
    const uint32_t bBase = sb + PJ_B0 + (wn*64 + (lane & 15))*272 + (lane >> 4)*16;
    const int aT[3] = {0, 1, 0}, bT[3] = {0, 0, 1};

    #pragma unroll
    for (int ch = 0; ch < 2; ch++) {
        #pragma unroll
        for (int t = 0; t < 3; t++) {
            #pragma unroll
            for (int ks = 0; ks < 4; ks++) {
                const uint32_t aOff = (uint32_t)(ch*34816 + aT[t]*128 + ks*32);
                const uint32_t bOff = (uint32_t)(ch*34816 + bT[t]*128 + ks*32);
                uint32_t afr[2][4];
                #pragma unroll
                for (int ma = 0; ma < 2; ma++)
                    LDM_X4(afr[ma][0], afr[ma][1], afr[ma][2], afr[ma][3],
                           aBase + ma*16*272 + aOff);
                uint32_t bfr[8][2];
                #pragma unroll
                for (int ng = 0; ng < 4; ng++) {
                    uint32_t d0, d1, d2, d3;
                    LDM_X4(d0, d1, d2, d3, bBase + ng*16*272 + bOff);
                    bfr[2*ng][0]   = d0; bfr[2*ng][1]   = d2;
                    bfr[2*ng+1][0] = d1; bfr[2*ng+1][1] = d3;
                }
                #pragma unroll
                for (int ma = 0; ma < 2; ma++)
                    #pragma unroll
                    for (int na = 0; na < 8; na++)
                        mma_bf16(acc[ma][na], afr[ma], bfr[na]);
            }
        }
    }
    __syncthreads();

    float* stage = (float*)smem;                 // [128][136]
    const float* biasS = (const float*)(smem + PJ_BIAS);
    #pragma unroll
    for (int ma = 0; ma < 2; ma++) {
        const int r0 = wm*32 + ma*16 + grp;
        #pragma unroll
        for (int na = 0; na < 8; na++) {
            const int c0 = wn*64 + na*8 + qr*2;
            stage[r0*136 + c0]     = acc[ma][na][0] + biasS[c0];
            stage[r0*136 + c0 + 1] = acc[ma][na][1] + biasS[c0 + 1];
            stage[(r0+8)*136 + c0]     = acc[ma][na][2] + biasS[c0];
            stage[(r0+8)*136 + c0 + 1] = acc[ma][na][3] + biasS[c0 + 1];
        }
    }
    __syncthreads();

    const int r = tid >> 1, h = tid & 1;
    if (nh == 0) {
        uint32_t hp[32], lp[32];
        #pragma unroll
        for (int k = 0; k < 32; k++) {
            float v0 = stage[r*136 + h*64 + 2*k];
            float v1 = stage[r*136 + h*64 + 2*k + 1];
            __nv_bfloat16 b0 = __float2bfloat16(v0), b1 = __float2bfloat16(v1);
            hp[k] = pack_b(b0, b1);
            lp[k] = pack_b(__float2bfloat16(v0 - __bfloat162float(b0)),
                           __float2bfloat16(v1 - __bfloat162float(b1)));
        }
        __nv_bfloat16* dstrow = (h == 0 ? g_Qs : g_Ks) + (size_t)(t0 + r) * 128;
        uint4* dh = (uint4*)dstrow;
        uint4* dl = (uint4*)(dstrow + 64);
        #pragma unroll
        for (int k = 0; k < 8; k++) { dh[k] = ((uint4*)hp)[k]; dl[k] = ((uint4*)lp)[k]; }
    } else {
        #pragma unroll
        for (int k = 0; k < 16; k++) {
            float4 v = *(const float4*)&stage[r*136 + h*64 + 4*k];
            *(float4*)&g_Vp[(size_t)(t0 + r) * 128 + h*64 + 4*k] = v;
        }
    }
}

// ---------------- kernel 2: scores (no stage, direct E store, 2 CTAs/SM) ---
#define SCQ 0
#define SCK0 34816
#define SCK1 69632
#define SC_SMEM 104448

__global__ __launch_bounds__(256, 2) void scores_kernel() {
    extern __shared__ char smem[];
    const uint32_t sb = smem_u32(smem);
    const int tid = threadIdx.x;
    const int wid = tid >> 5, lane = tid & 31;
    const int grp = lane >> 2, qr = lane & 3;
    const int wm = wid >> 1, wn = wid & 1;
    const int b = blockIdx.y;

    int qt, g0, g1;
    decode_qt(blockIdx.x, qt, g0, g1);
    const int nk = g1 - g0;
    const int q0 = qt * 128;

    const char* Qsrc = (const char*)(g_Qs + (size_t)(b * Sc + q0) * 128);
    const char* Kbase = (const char*)(g_Ks + (size_t)b * Sc * 128);

    for (int idx = tid; idx < 2048; idx += 256) {
        int r = idx >> 4, ch = idx & 15;
        CP16(sb + SCQ + r*272 + ch*16, Qsrc + r*256 + ch*16);
        CP16(sb + SCK0 + r*272 + ch*16, Kbase + (size_t)(g0*128 + r)*256 + ch*16);
    }
    CP_COMMIT();

    const uint32_t aBase = sb + SCQ + (wm*32 + (lane & 15))*272 + (lane >> 4)*16;
    const uint32_t lmRow = (uint32_t)((wn*64 + (lane & 15))*272 + (lane >> 4)*16);
    const int aT[3] = {0, 1, 0}, bT[3] = {0, 0, 1};
    const float C = 0.18033688011112042f;   // 0.125 * log2(e)

    for (int i = 0; i < nk; i++) {
        const uint32_t kbuf = (i & 1) ? SCK1 : SCK0;
        if (i + 1 < nk) {
            const uint32_t nbuf = ((i + 1) & 1) ? SCK1 : SCK0;
            const size_t joff = (size_t)((g0 + i + 1) * 128) * 256;
            for (int idx = tid; idx < 2048; idx += 256) {
                int r = idx >> 4, ch = idx & 15;
                CP16(sb + nbuf + r*272 + ch*16, Kbase + joff + r*256 + ch*16);
            }
            CP_COMMIT();
            CP_WAITG(1);
        } else {
            CP_WAITG(0);
        }
        __syncthreads();

        float acc[2][8][4] = {};
        const uint32_t bBase = sb + kbuf + lmRow;
        #pragma unroll
        for (int t = 0; t < 3; t++) {
            #pragma unroll
            for (int ks = 0; ks < 4; ks++) {
                const uint32_t aOff = (uint32_t)(aT[t]*128 + ks*32);
                const uint32_t bOff = (uint32_t)(bT[t]*128 + ks*32);
                uint32_t afr[2][4];
                #pragma unroll
                for (int ma = 0; ma < 2; ma++)
                    LDM_X4(afr[ma][0], afr[ma][1], afr[ma][2], afr[ma][3],
                           aBase + ma*16*272 + aOff);
                uint32_t bfr[8][2];
                #pragma unroll
                for (int ng = 0; ng < 4; ng++) {
                    uint32_t d0, d1, d2, d3;
                    LDM_X4(d0, d1, d2, d3, bBase + ng*16*272 + bOff);
                    bfr[2*ng][0]   = d0; bfr[2*ng][1]   = d2;
                    bfr[2*ng+1][0] = d1; bfr[2*ng+1][1] = d3;
                }
                #pragma unroll
                for (int ma = 0; ma < 2; ma++)
                    #pragma unroll
                    for (int na = 0; na < 8; na++)
                        mma_bf16(acc[ma][na], afr[ma], bfr[na]);
            }
        }

        // epilogue: exp -> direct E store + in-register column sums
        const int j0 = (g0 + i) * 128;
        float cs0[8] = {}, cs1[8] = {};
        #pragma unroll
        for (int ma = 0; ma < 2; ma++) {
            const int r0 = wm*32 + ma*16 + grp;
            const int qlo = q0 + r0, qhi = qlo + 8;
            __half* row0 = g_E + (size_t)(b * Sc + q0 + r0) * Sc;
            __half* row1 = row0 + (size_t)8 * Sc;
            #pragma unroll
            for (int na = 0; na < 8; na++) {
                const int c0 = wn*64 + na*8 + qr*2;
                const int jc = j0 + c0;
                float t0 = (jc     <= qlo) ? acc[ma][na][0] * C : -1000.0f;
                float t1 = (jc + 1 <= qlo) ? acc[ma][na][1] * C : -1000.0f;
                float t2 = (jc     <= qhi) ? acc[ma][na][2] * C : -1000.0f;
                float t3 = (jc + 1 <= qhi) ? acc[ma][na][3] * C : -1000.0f;
                uint32_t u0 = exp2h2(t0, t1), u1 = exp2h2(t2, t3);
                *(uint32_t*)&row0[jc] = u0;
                *(uint32_t*)&row1[jc] = u1;
                __half2 e0 = *reinterpret_cast<__half2*>(&u0);
                __half2 e1 = *reinterpret_cast<__half2*>(&u1);
                cs0[na] += __low2float(e0)  + __low2float(e1);
                cs1[na] += __high2float(e0) + __high2float(e1);
            }
        }
        #pragma unroll
        for (int na = 0; na < 8; na++) {
            #pragma unroll
            for (int m = 4; m <= 16; m <<= 1) {
                cs0[na] += __shfl_xor_sync(0xFFFFFFFFu, cs0[na], m);
                cs1[na] += __shfl_xor_sync(0xFFFFFFFFu, cs1[na], m);
            }
        }
        if (grp == 0) {
            #pragma unroll
            for (int na = 0; na < 8; na++) {
                const int jc = j0 + wn*64 + na*8 + qr*2;
                atomicAdd(&g_denom[b * Sc + jc],     cs0[na]);
                atomicAdd(&g_denom[b * Sc + jc + 1], cs1[na]);
            }
        }
        __syncthreads();   // kbuf must be fully consumed before reuse
    }
}

// ---------------- kernel 3: vprep ----------------
__global__ __launch_bounds__(256) void vprep_kernel() {
    __shared__ float tile[32][133];
    __shared__ float invs[32];
    const int b = blockIdx.y, s0 = blockIdx.x * 32, tid = threadIdx.x;
    if (tid < 32) invs[tid] = 1.0f / g_denom[b * Sc + s0 + tid];
    __syncthreads();
    #pragma unroll
    for (int i = 0; i < 16; i++) {
        int idx = tid + i * 256;
        int r = idx >> 7, c = idx & 127;
        tile[r][c] = g_Vp[(size_t)(b * Sc + s0 + r) * Vc + c] * invs[r];
    }
    __syncthreads();
    const int v = tid >> 1, h = tid & 1;
    uint32_t packs[8];
    #pragma unroll
    for (int k = 0; k < 8; k++)
        packs[k] = pack_h(__float2half(tile[h*16 + 2*k][v]),
                          __float2half(tile[h*16 + 2*k + 1][v]));
    uint4* dst = (uint4*)(g_Vt + (size_t)(b * Vc + v) * Sc + s0 + h*16);
    dst[0] = ((uint4*)packs)[0];
    dst[1] = ((uint4*)packs)[1];
}

// ---------------- kernel 4: attn (64-col chunks, quad-buffer, 2 CTAs/SM) ---
#define AE0 0
#define AV0 18432
#define AE1 36864
#define AV1 55296
#define AT_SMEM 73728

__global__ __launch_bounds__(256, 2) void attn_kernel(float* __restrict__ out) {
    extern __shared__ char smem[];
    const uint32_t sb = smem_u32(smem);
    const int tid = threadIdx.x;
    const int wid = tid >> 5, lane = tid & 31;
    const int grp = lane >> 2, qr = lane & 3;
    const int wm = wid >> 1, wn = wid & 1;
    const int b = blockIdx.y;

    int qt, g0, g1;
    decode_qt(blockIdx.x, qt, g0, g1);
    const int nc = 2 * (g1 - g0);     // 64-col chunks
    const int c0base = 2 * g0;
    const int q0 = qt * 128;

    const char* Ebase = (const char*)g_E + (size_t)(b*Sc + q0) * Sc * 2;
    const char* Vbase = (const char*)g_Vt + (size_t)b * Vc * Sc * 2;

    // initial fill: chunk 0
    {
        const int jbyte = c0base * 128;
        for (int idx = tid; idx < 1024; idx += 256) {
            int r = idx >> 3, ch = idx & 7;
            CP16(sb + AE0 + r*144 + ch*16, Ebase + (size_t)r*Sc*2 + jbyte + ch*16);
            CP16(sb + AV0 + r*144 + ch*16, Vbase + (size_t)r*Sc*2 + jbyte + ch*16);
        }
        CP_COMMIT();
    }

    float acc[2][8][4] = {};
    const uint32_t lmA = (uint32_t)((wm*32 + (lane & 15))*144 + (lane >> 4)*16);
    const uint32_t lmB = (uint32_t)((wn*64 + (lane & 15))*144 + (lane >> 4)*16);

    for (int i = 0; i < nc; i++) {
        const uint32_t ebuf = (i & 1) ? AE1 : AE0;
        const uint32_t vbuf = (i & 1) ? AV1 : AV0;
        if (i + 1 < nc) {
            const uint32_t ne = ((i + 1) & 1) ? AE1 : AE0;
            const uint32_t nv = ((i + 1) & 1) ? AV1 : AV0;
            const int jbyte = (c0base + i + 1) * 128;
            for (int idx = tid; idx < 1024; idx += 256) {
                int r = idx >> 3, ch = idx & 7;
                CP16(sb + ne + r*144 + ch*16, Ebase + (size_t)r*Sc*2 + jbyte + ch*16);
                CP16(sb + nv + r*144 + ch*16, Vbase + (size_t)r*Sc*2 + jbyte + ch*16);
            }
            CP_COMMIT();
            CP_WAITG(1);
        } else {
            CP_WAITG(0);
        }
        __syncthreads();

        const uint32_t aBase = sb + ebuf + lmA;
        const uint32_t bBase = sb + vbuf + lmB;
        #pragma unroll
        for (int ks = 0; ks < 4; ks++) {
            const uint32_t kOff = (uint32_t)(ks * 32);
            uint32_t afr[2][4];
            #pragma unroll
            for (int ma = 0; ma < 2; ma++)
                LDM_X4(afr[ma][0], afr[ma][1], afr[ma][2], afr[ma][3],
                       aBase + ma*16*144 + kOff);
            uint32_t bfr[8][2];
            #pragma unroll
            for (int ng = 0; ng < 4; ng++) {
                uint32_t d0, d1, d2, d3;
                LDM_X4(d0, d1, d2, d3, bBase + ng*16*144 + kOff);
                bfr[2*ng][0]   = d0; bfr[2*ng][1]   = d2;
                bfr[2*ng+1][0] = d1; bfr[2*ng+1][1] = d3;
            }
            #pragma unroll
            for (int ma = 0; ma < 2; ma++)
                #pragma unroll
                for (int na = 0; na < 8; na++)
                    mma_f16(acc[ma][na], afr[ma], bfr[na]);
        }
        __syncthreads();
    }

    #pragma unroll
    for (int ma = 0; ma < 2; ma++) {
        const int r0 = q0 + wm*32 + ma*16 + grp;
        #pragma unroll
        for (int na = 0; na < 8; na++) {
            const int v0 = wn*64 + na*8 + qr*2;
            atomicAdd(&out[(size_t)(b*Sc + r0)*OUTC + Dc + v0],     acc[ma][na][0]);
            atomicAdd(&out[(size_t)(b*Sc + r0)*OUTC + Dc + v0 + 1], acc[ma][na][1]);
            atomicAdd(&out[(size_t)(b*Sc + r0 + 8)*OUTC + Dc + v0],     acc[ma][na][2]);
            atomicAdd(&out[(size_t)(b*Sc + r0 + 8)*OUTC + Dc + v0 + 1], acc[ma][na][3]);
        }
    }
}

// ---------------- launch ----------------
extern "C" void kernel_launch(void* const* d_in, const int* in_sizes, int n_in,
                              void* d_out, int out_size) {
    const float* x  = (const float*)d_in[0];
    const float* Wq = (const float*)d_in[1];
    const float* bq = (const float*)d_in[2];
    const float* Wk = (const float*)d_in[3];
    const float* bk = (const float*)d_in[4];
    const float* Wv = (const float*)d_in[5];
    const float* bv = (const float*)d_in[6];
    float* out = (float*)d_out;

    cudaFuncSetAttribute(proj_kernel,   cudaFuncAttributeMaxDynamicSharedMemorySize, PJ_SMEM);
    cudaFuncSetAttribute(scores_kernel, cudaFuncAttributeMaxDynamicSharedMemorySize, SC_SMEM);
    cudaFuncSetAttribute(attn_kernel,   cudaFuncAttributeMaxDynamicSharedMemorySize, AT_SMEM);

    proj_kernel<<<dim3(BSc / 128, 2), 256, PJ_SMEM>>>(x, Wq, bq, Wk, bk, Wv, bv, out);
    scores_kernel<<<dim3(80, Bc), 256, SC_SMEM>>>();
    vprep_kernel<<<dim3(Sc / 32, Bc), 256>>>();
    attn_kernel<<<dim3(80, Bc), 256, AT_SMEM>>>(out);
}

// round 14
// speedup vs baseline: 1.6402x; 1.3543x over previous
#include <cuda_runtime.h>
#include <cuda_bf16.h>
#include <cuda_fp16.h>
#include <cstdint>

#define Bc 4
#define Sc 4096
#define Dc 128
#define Kc 64
#define Vc 128
#define BSc (Bc*Sc)
#define OUTC 256

// ---------------- scratch ----------------
__device__ __half g_Qs[(size_t)BSc * 64];              // fp16 Q rows
__device__ __half g_Ks[(size_t)BSc * 64];              // fp16 K rows
__device__ float  g_Vp[(size_t)BSc * Vc];
__device__ __half g_E[(size_t)Bc * Sc * Sc];           // exp(scores), causal zeros
__device__ __half g_Vt[(size_t)Bc * Vc * Sc];          // [b][v][s], V/denom, fp16
__device__ float  g_denom[BSc];

// ---------------- PTX helpers ----------------
__device__ __forceinline__ uint32_t smem_u32(const void* p) {
    uint32_t a;
    asm("{ .reg .u64 t; cvta.to.shared.u64 t, %1; cvt.u32.u64 %0, t; }" : "=r"(a) : "l"(p));
    return a;
}
#define CP16(dst, src) \
    asm volatile("cp.async.cg.shared.global [%0], [%1], 16;" :: "r"(dst), "l"(src))
#define CP_COMMIT() asm volatile("cp.async.commit_group;" ::: "memory")
#define CP_WAITG(n) asm volatile("cp.async.wait_group %0;" :: "n"(n) : "memory")
#define LDM_X4(d0, d1, d2, d3, a) \
    asm volatile("ldmatrix.sync.aligned.m8n8.x4.shared.b16 {%0,%1,%2,%3}, [%4];" \
        : "=r"(d0), "=r"(d1), "=r"(d2), "=r"(d3) : "r"(a))

__device__ __forceinline__ void mma_bf16(float* d, const uint32_t* a, const uint32_t* b) {
    asm volatile("mma.sync.aligned.m16n8k16.row.col.f32.bf16.bf16.f32 "
        "{%0,%1,%2,%3}, {%4,%5,%6,%7}, {%8,%9}, {%0,%1,%2,%3};"
        : "+f"(d[0]), "+f"(d[1]), "+f"(d[2]), "+f"(d[3])
        : "r"(a[0]), "r"(a[1]), "r"(a[2]), "r"(a[3]), "r"(b[0]), "r"(b[1]));
}
__device__ __forceinline__ void mma_f16(float* d, const uint32_t* a, const uint32_t* b) {
    asm volatile("mma.sync.aligned.m16n8k16.row.col.f32.f16.f16.f32 "
        "{%0,%1,%2,%3}, {%4,%5,%6,%7}, {%8,%9}, {%0,%1,%2,%3};"
        : "+f"(d[0]), "+f"(d[1]), "+f"(d[2]), "+f"(d[3])
        : "r"(a[0]), "r"(a[1]), "r"(a[2]), "r"(a[3]), "r"(b[0]), "r"(b[1]));
}
__device__ __forceinline__ uint32_t pack_h(__half a, __half b) {
    __half2 t; t.x = a; t.y = b;
    return *reinterpret_cast<uint32_t*>(&t);
}
__device__ __forceinline__ uint32_t pack_b(__nv_bfloat16 a, __nv_bfloat16 b) {
    __nv_bfloat162 t; t.x = a; t.y = b;
    return *reinterpret_cast<uint32_t*>(&t);
}

// exp(s/8) as 2^(s*C): ex2.approx.f16x2 + fp32 residual correction.
__device__ __forceinline__ uint32_t exp2h2(float t0, float t1) {
    __half2 th = __floats2half2_rn(t0, t1);
    uint32_t thu = *reinterpret_cast<uint32_t*>(&th);
    uint32_t eu;
    asm("ex2.approx.f16x2 %0, %1;" : "=r"(eu) : "r"(thu));
    float tl0 = t0 - __half2float(__low2half(th));
    float tl1 = t1 - __half2float(__high2half(th));
    __half2 c = __floats2half2_rn(fmaf(0.6931472f, tl0, 1.0f),
                                  fmaf(0.6931472f, tl1, 1.0f));
    __half2 e = *reinterpret_cast<__half2*>(&eu);
    e = __hmul2(e, c);
    return *reinterpret_cast<uint32_t*>(&e);
}

// causal (qt, group-of-8) decode, heaviest first; sum over qt of ceil((qt+1)/8) = 80
__device__ __forceinline__ void decode_qt(int bx, int& qt, int& g0, int& g1) {
    int lin = 79 - bx;
    int base = 0; qt = 0;
    for (;;) { int gq = (qt + 8) >> 3; if (lin < base + gq) break; base += gq; qt++; }
    g0 = (lin - base) * 8;
    g1 = min(qt + 1, g0 + 8);
}

// ---------------- kernel 1: projections (mma split-bf16) -------------------
// nh==0 CTAs also write out[:, :128] = x and zero out[:, 128:256].
#define PJ_A0 0
#define PJ_A1 34816
#define PJ_B0 69632
#define PJ_B1 104448
#define PJ_BIAS 139264
#define PJ_SMEM 139776

__global__ __launch_bounds__(256) void proj_kernel(
    const float* __restrict__ x,
    const float* __restrict__ Wq, const float* __restrict__ bq,
    const float* __restrict__ Wk, const float* __restrict__ bk,
    const float* __restrict__ Wv, const float* __restrict__ bv,
    float* __restrict__ out) {
    extern __shared__ char smem[];
    const uint32_t sb = smem_u32(smem);
    const int tid = threadIdx.x;
    const int wid = tid >> 5, lane = tid & 31;
    const int grp = lane >> 2, qr = lane & 3;
    const int wm = wid >> 1, wn = wid & 1;
    const int nh = blockIdx.y;
    const int t0 = blockIdx.x * 128;

    if (nh == 0) {
        int i = blockIdx.x * 256 + tid;
        if (i < BSc) g_denom[i] = 0.0f;
    }
    if (tid < 128) {
        float bvv = (nh == 0) ? ((tid < 64) ? bq[tid] : bk[tid - 64]) : bv[tid];
        ((float*)(smem + PJ_BIAS))[tid] = bvv;
    }

    #pragma unroll
    for (int i = 0; i < 16; i++) {
        int idx = tid + i * 256;
        int r = idx >> 5, c4 = idx & 31;
        int ch = c4 >> 4, cc = c4 & 15;
        float4 a = *(const float4*)&x[(size_t)(t0 + r) * 128 + c4 * 4];
        if (nh == 0) {   // fused concat: out[:, :128] = x, out[:, 128:] = 0
            ((float4*)out)[(size_t)(t0 + r) * 64 + c4] = a;
            ((float4*)out)[(size_t)(t0 + r) * 64 + 32 + c4] =
                make_float4(0.f, 0.f, 0.f, 0.f);
        }
        __nv_bfloat16 h0 = __float2bfloat16(a.x), h1 = __float2bfloat16(a.y);
        __nv_bfloat16 h2 = __float2bfloat16(a.z), h3 = __float2bfloat16(a.w);
        uint2 hi = make_uint2(pack_b(h0, h1), pack_b(h2, h3));
        uint2 lo = make_uint2(
            pack_b(__float2bfloat16(a.x - __bfloat162float(h0)),
                   __float2bfloat16(a.y - __bfloat162float(h1))),
            pack_b(__float2bfloat16(a.z - __bfloat162float(h2)),
                   __float2bfloat16(a.w - __bfloat162float(h3))));
        char* ab = smem + (ch ? PJ_A1 : PJ_A0) + r * 272 + cc * 8;
        *(uint2*)ab = hi;
        *(uint2*)(ab + 128) = lo;

        const float* wsrc = (nh == 0)
            ? ((r < 64) ? (Wq + (size_t)r * 128) : (Wk + (size_t)(r - 64) * 128))
            : (Wv + (size_t)r * 128);
        float4 w = *(const float4*)&wsrc[c4 * 4];
        __nv_bfloat16 g0 = __float2bfloat16(w.x), g1 = __float2bfloat16(w.y);
        __nv_bfloat16 g2 = __float2bfloat16(w.z), g3 = __float2bfloat16(w.w);
        uint2 whi = make_uint2(pack_b(g0, g1), pack_b(g2, g3));
        uint2 wlo = make_uint2(
            pack_b(__float2bfloat16(w.x - __bfloat162float(g0)),
                   __float2bfloat16(w.y - __bfloat162float(g1))),
            pack_b(__float2bfloat16(w.z - __bfloat162float(g2)),
                   __float2bfloat16(w.w - __bfloat162float(g3))));
        char* bb = smem + (ch ? PJ_B1 : PJ_B0) + r * 272 + cc * 8;
        *(uint2*)bb = whi;
        *(uint2*)(bb + 128) = wlo;
    }
    __syncthreads();

    float acc[2][8][4] = {};
    const uint32_t aBase = sb + PJ_A0 + (wm*32 + (lane & 15))*272 + (lane >> 4)*16;
    const uint32_t bBase = sb + PJ_B0 + (wn*64 + (lane & 15))*272 + (lane >> 4)*16;
    const int aT[3] = {0, 1, 0}, bT[3] = {0, 0, 1};

    #pragma unroll
    for (int ch = 0; ch < 2; ch++) {
        #pragma unroll
        for (int t = 0; t < 3; t++) {
            #pragma unroll
            for (int ks = 0; ks < 4; ks++) {
                const uint32_t aOff = (uint32_t)(ch*34816 + aT[t]*128 + ks*32);
                const uint32_t bOff = (uint32_t)(ch*34816 + bT[t]*128 + ks*32);
                uint32_t afr[2][4];
                #pragma unroll
                for (int ma = 0; ma < 2; ma++)
                    LDM_X4(afr[ma][0], afr[ma][1], afr[ma][2], afr[ma][3],
                           aBase + ma*16*272 + aOff);
                uint32_t bfr[8][2];
                #pragma unroll
                for (int ng = 0; ng < 4; ng++) {
                    uint32_t d0, d1, d2, d3;
                    LDM_X4(d0, d1, d2, d3, bBase + ng*16*272 + bOff);
                    bfr[2*ng][0]   = d0; bfr[2*ng][1]   = d2;
                    bfr[2*ng+1][0] = d1; bfr[2*ng+1][1] = d3;
                }
                #pragma unroll
                for (int ma = 0; ma < 2; ma++)
                    #pragma unroll
                    for (int na = 0; na < 8; na++)
                        mma_bf16(acc[ma][na], afr[ma], bfr[na]);
            }
        }
    }
    __syncthreads();

    float* stage = (float*)smem;                 // [128][136]
    const float* biasS = (const float*)(smem + PJ_BIAS);
    #pragma unroll
    for (int ma = 0; ma < 2; ma++) {
        const int r0 = wm*32 + ma*16 + grp;
        #pragma unroll
        for (int na = 0; na < 8; na++) {
            const int c0 = wn*64 + na*8 + qr*2;
            stage[r0*136 + c0]     = acc[ma][na][0] + biasS[c0];
            stage[r0*136 + c0 + 1] = acc[ma][na][1] + biasS[c0 + 1];
            stage[(r0+8)*136 + c0]     = acc[ma][na][2] + biasS[c0];
            stage[(r0+8)*136 + c0 + 1] = acc[ma][na][3] + biasS[c0 + 1];
        }
    }
    __syncthreads();

    const int r = tid >> 1, h = tid & 1;
    if (nh == 0) {
        // h=0 -> Q row (stage cols 0..63), h=1 -> K row (stage cols 64..127)
        // FULL 64-half row: hp[32] = 64 values = 8 x uint4  (R13 bug: wrote 32)
        uint32_t hp[32];
        #pragma unroll
        for (int k = 0; k < 32; k++) {
            float v0 = stage[r*136 + h*64 + 2*k];
            float v1 = stage[r*136 + h*64 + 2*k + 1];
            hp[k] = pack_h(__float2half(v0), __float2half(v1));
        }
        __half* dstrow = (h == 0 ? g_Qs : g_Ks) + (size_t)(t0 + r) * 64;
        uint4* dh = (uint4*)dstrow;
        #pragma unroll
        for (int k = 0; k < 8; k++) dh[k] = ((uint4*)hp)[k];
    } else {
        #pragma unroll
        for (int k = 0; k < 16; k++) {
            float4 v = *(const float4*)&stage[r*136 + h*64 + 4*k];
            *(float4*)&g_Vp[(size_t)(t0 + r) * 128 + h*64 + 4*k] = v;
        }
    }
}

// ---------------- kernel 2: scores (fp16 single-term, 4 ksteps) ------------
// Q resident (18KB), K double-buffered (2x18KB); smem 54KB, 2 CTAs/SM.
#define SCQ 0
#define SCK0 18432
#define SCK1 36864
#define SC_SMEM 55296

__global__ __launch_bounds__(256, 2) void scores_kernel() {
    extern __shared__ char smem[];
    const uint32_t sb = smem_u32(smem);
    const int tid = threadIdx.x;
    const int wid = tid >> 5, lane = tid & 31;
    const int grp = lane >> 2, qr = lane & 3;
    const int wm = wid >> 1, wn = wid & 1;
    const int b = blockIdx.y;

    int qt, g0, g1;
    decode_qt(blockIdx.x, qt, g0, g1);
    const int nk = g1 - g0;
    const int q0 = qt * 128;

    const char* Qsrc = (const char*)(g_Qs + (size_t)(b * Sc + q0) * 64);
    const char* Kbase = (const char*)(g_Ks + (size_t)b * Sc * 64);

    for (int idx = tid; idx < 1024; idx += 256) {
        int r = idx >> 3, ch = idx & 7;
        CP16(sb + SCQ + r*144 + ch*16, Qsrc + r*128 + ch*16);
        CP16(sb + SCK0 + r*144 + ch*16, Kbase + (size_t)(g0*128 + r)*128 + ch*16);
    }
    CP_COMMIT();

    const uint32_t aBase = sb + SCQ + (wm*32 + (lane & 15))*144 + (lane >> 4)*16;
    const uint32_t lmRow = (uint32_t)((wn*64 + (lane & 15))*144 + (lane >> 4)*16);
    const float C = 0.18033688011112042f;   // 0.125 * log2(e)

    for (int i = 0; i < nk; i++) {
        const uint32_t kbuf = (i & 1) ? SCK1 : SCK0;
        if (i + 1 < nk) {
            const uint32_t nbuf = ((i + 1) & 1) ? SCK1 : SCK0;
            const size_t joff = (size_t)((g0 + i + 1) * 128) * 128;
            for (int idx = tid; idx < 1024; idx += 256) {
                int r = idx >> 3, ch = idx & 7;
                CP16(sb + nbuf + r*144 + ch*16, Kbase + joff + r*128 + ch*16);
            }
            CP_COMMIT();
            CP_WAITG(1);
        } else {
            CP_WAITG(0);
        }
        __syncthreads();

        float acc[2][8][4] = {};
        const uint32_t bBase = sb + kbuf + lmRow;
        #pragma unroll
        for (int ks = 0; ks < 4; ks++) {
            const uint32_t kOff = (uint32_t)(ks * 32);
            uint32_t afr[2][4];
            #pragma unroll
            for (int ma = 0; ma < 2; ma++)
                LDM_X4(afr[ma][0], afr[ma][1], afr[ma][2], afr[ma][3],
                       aBase + ma*16*144 + kOff);
            uint32_t bfr[8][2];
            #pragma unroll
            for (int ng = 0; ng < 4; ng++) {
                uint32_t d0, d1, d2, d3;
                LDM_X4(d0, d1, d2, d3, bBase + ng*16*144 + kOff);
                bfr[2*ng][0]   = d0; bfr[2*ng][1]   = d2;
                bfr[2*ng+1][0] = d1; bfr[2*ng+1][1] = d3;
            }
            #pragma unroll
            for (int ma = 0; ma < 2; ma++)
                #pragma unroll
                for (int na = 0; na < 8; na++)
                    mma_f16(acc[ma][na], afr[ma], bfr[na]);
        }

        // epilogue: exp -> direct E store + in-register column sums
        const int j0 = (g0 + i) * 128;
        float cs0[8] = {}, cs1[8] = {};
        #pragma unroll
        for (int ma = 0; ma < 2; ma++) {
            const int r0 = wm*32 + ma*16 + grp;
            const int qlo = q0 + r0, qhi = qlo + 8;
            __half* row0 = g_E + (size_t)(b * Sc + q0 + r0) * Sc;
            __half* row1 = row0 + (size_t)8 * Sc;
            #pragma unroll
            for (int na = 0; na < 8; na++) {
                const int c0 = wn*64 + na*8 + qr*2;
                const int jc = j0 + c0;
                float t0 = (jc     <= qlo) ? acc[ma][na][0] * C : -1000.0f;
                float t1 = (jc + 1 <= qlo) ? acc[ma][na][1] * C : -1000.0f;
                float t2 = (jc     <= qhi) ? acc[ma][na][2] * C : -1000.0f;
                float t3 = (jc + 1 <= qhi) ? acc[ma][na][3] * C : -1000.0f;
                uint32_t u0 = exp2h2(t0, t1), u1 = exp2h2(t2, t3);
                *(uint32_t*)&row0[jc] = u0;
                *(uint32_t*)&row1[jc] = u1;
                __half2 e0 = *reinterpret_cast<__half2*>(&u0);
                __half2 e1 = *reinterpret_cast<__half2*>(&u1);
                cs0[na] += __low2float(e0)  + __low2float(e1);
                cs1[na] += __high2float(e0) + __high2float(e1);
            }
        }
        #pragma unroll
        for (int na = 0; na < 8; na++) {
            #pragma unroll
            for (int m = 4; m <= 16; m <<= 1) {
                cs0[na] += __shfl_xor_sync(0xFFFFFFFFu, cs0[na], m);
                cs1[na] += __shfl_xor_sync(0xFFFFFFFFu, cs1[na], m);
            }
        }
        if (grp == 0) {
            #pragma unroll
            for (int na = 0; na < 8; na++) {
                const int jc = j0 + wn*64 + na*8 + qr*2;
                atomicAdd(&g_denom[b * Sc + jc],     cs0[na]);
                atomicAdd(&g_denom[b * Sc + jc + 1], cs1[na]);
            }
        }
        __syncthreads();   // kbuf must be fully consumed before reuse
    }
}

// ---------------- kernel 3: vprep ----------------
__global__ __launch_bounds__(256) void vprep_kernel() {
    __shared__ float tile[32][133];
    __shared__ float invs[32];
    const int b = blockIdx.y, s0 = blockIdx.x * 32, tid = threadIdx.x;
    if (tid < 32) invs[tid] = 1.0f / g_denom[b * Sc + s0 + tid];
    __syncthreads();
    #pragma unroll
    for (int i = 0; i < 16; i++) {
        int idx = tid + i * 256;
        int r = idx >> 7, c = idx & 127;
        tile[r][c] = g_Vp[(size_t)(b * Sc + s0 + r) * Vc + c] * invs[r];
    }
    __syncthreads();
    const int v = tid >> 1, h = tid & 1;
    uint32_t packs[8];
    #pragma unroll
    for (int k = 0; k < 8; k++)
        packs[k] = pack_h(__float2half(tile[h*16 + 2*k][v]),
                          __float2half(tile[h*16 + 2*k + 1][v]));
    uint4* dst = (uint4*)(g_Vt + (size_t)(b * Vc + v) * Sc + s0 + h*16);
    dst[0] = ((uint4*)packs)[0];
    dst[1] = ((uint4*)packs)[1];
}

// ---------------- kernel 4: attn (64-col chunks, quad-buffer, 2 CTAs/SM) ---
#define AE0 0
#define AV0 18432
#define AE1 36864
#define AV1 55296
#define AT_SMEM 73728

__global__ __launch_bounds__(256, 2) void attn_kernel(float* __restrict__ out) {
    extern __shared__ char smem[];
    const uint32_t sb = smem_u32(smem);
    const int tid = threadIdx.x;
    const int wid = tid >> 5, lane = tid & 31;
    const int grp = lane >> 2, qr = lane & 3;
    const int wm = wid >> 1, wn = wid & 1;
    const int b = blockIdx.y;

    int qt, g0, g1;
    decode_qt(blockIdx.x, qt, g0, g1);
    const int nc = 2 * (g1 - g0);     // 64-col chunks
    const int c0base = 2 * g0;
    const int q0 = qt * 128;

    const char* Ebase = (const char*)g_E + (size_t)(b*Sc + q0) * Sc * 2;
    const char* Vbase = (const char*)g_Vt + (size_t)b * Vc * Sc * 2;

    {
        const int jbyte = c0base * 128;
        for (int idx = tid; idx < 1024; idx += 256) {
            int r = idx >> 3, ch = idx & 7;
            CP16(sb + AE0 + r*144 + ch*16, Ebase + (size_t)r*Sc*2 + jbyte + ch*16);
            CP16(sb + AV0 + r*144 + ch*16, Vbase + (size_t)r*Sc*2 + jbyte + ch*16);
        }
        CP_COMMIT();
    }

    float acc[2][8][4] = {};
    const uint32_t lmA = (uint32_t)((wm*32 + (lane & 15))*144 + (lane >> 4)*16);
    const uint32_t lmB = (uint32_t)((wn*64 + (lane & 15))*144 + (lane >> 4)*16);

    for (int i = 0; i < nc; i++) {
        const uint32_t ebuf = (i & 1) ? AE1 : AE0;
        const uint32_t vbuf = (i & 1) ? AV1 : AV0;
        if (i + 1 < nc) {
            const uint32_t ne = ((i + 1) & 1) ? AE1 : AE0;
            const uint32_t nv = ((i + 1) & 1) ? AV1 : AV0;
            const int jbyte = (c0base + i + 1) * 128;
            for (int idx = tid; idx < 1024; idx += 256) {
                int r = idx >> 3, ch = idx & 7;
                CP16(sb + ne + r*144 + ch*16, Ebase + (size_t)r*Sc*2 + jbyte + ch*16);
                CP16(sb + nv + r*144 + ch*16, Vbase + (size_t)r*Sc*2 + jbyte + ch*16);
            }
            CP_COMMIT();
            CP_WAITG(1);
        } else {
            CP_WAITG(0);
        }
        __syncthreads();

        const uint32_t aBase = sb + ebuf + lmA;
        const uint32_t bBase = sb + vbuf + lmB;
        #pragma unroll
        for (int ks = 0; ks < 4; ks++) {
            const uint32_t kOff = (uint32_t)(ks * 32);
            uint32_t afr[2][4];
            #pragma unroll
            for (int ma = 0; ma < 2; ma++)
                LDM_X4(afr[ma][0], afr[ma][1], afr[ma][2], afr[ma][3],
                       aBase + ma*16*144 + kOff);
            uint32_t bfr[8][2];
            #pragma unroll
            for (int ng = 0; ng < 4; ng++) {
                uint32_t d0, d1, d2, d3;
                LDM_X4(d0, d1, d2, d3, bBase + ng*16*144 + kOff);
                bfr[2*ng][0]   = d0; bfr[2*ng][1]   = d2;
                bfr[2*ng+1][0] = d1; bfr[2*ng+1][1] = d3;
            }
            #pragma unroll
            for (int ma = 0; ma < 2; ma++)
                #pragma unroll
                for (int na = 0; na < 8; na++)
                    mma_f16(acc[ma][na], afr[ma], bfr[na]);
        }
        __syncthreads();
    }

    #pragma unroll
    for (int ma = 0; ma < 2; ma++) {
        const int r0 = q0 + wm*32 + ma*16 + grp;
        #pragma unroll
        for (int na = 0; na < 8; na++) {
            const int v0 = wn*64 + na*8 + qr*2;
            atomicAdd(&out[(size_t)(b*Sc + r0)*OUTC + Dc + v0],     acc[ma][na][0]);
            atomicAdd(&out[(size_t)(b*Sc + r0)*OUTC + Dc + v0 + 1], acc[ma][na][1]);
            atomicAdd(&out[(size_t)(b*Sc + r0 + 8)*OUTC + Dc + v0],     acc[ma][na][2]);
            atomicAdd(&out[(size_t)(b*Sc + r0 + 8)*OUTC + Dc + v0 + 1], acc[ma][na][3]);
        }
    }
}

// ---------------- launch ----------------
extern "C" void kernel_launch(void* const* d_in, const int* in_sizes, int n_in,
                              void* d_out, int out_size) {
    const float* x  = (const float*)d_in[0];
    const float* Wq = (const float*)d_in[1];
    const float* bq = (const float*)d_in[2];
    const float* Wk = (const float*)d_in[3];
    const float* bk = (const float*)d_in[4];
    const float* Wv = (const float*)d_in[5];
    const float* bv = (const float*)d_in[6];
    float* out = (float*)d_out;

    cudaFuncSetAttribute(proj_kernel,   cudaFuncAttributeMaxDynamicSharedMemorySize, PJ_SMEM);
    cudaFuncSetAttribute(scores_kernel, cudaFuncAttributeMaxDynamicSharedMemorySize, SC_SMEM);
    cudaFuncSetAttribute(attn_kernel,   cudaFuncAttributeMaxDynamicSharedMemorySize, AT_SMEM);

    proj_kernel<<<dim3(BSc / 128, 2), 256, PJ_SMEM>>>(x, Wq, bq, Wk, bk, Wv, bv, out);
    scores_kernel<<<dim3(80, Bc), 256, SC_SMEM>>>();
    vprep_kernel<<<dim3(Sc / 32, Bc), 256>>>();
    attn_kernel<<<dim3(80, Bc), 256, AT_SMEM>>>(out);
}